// round 13
// baseline (speedup 1.0000x reference)
#include <cuda_runtime.h>
#include <cuda_bf16.h>
#include <math.h>
#include <stdint.h>

#define Bsz 2
#define Ssz 2048
#define Dsz 1024
#define Hsz 16
#define DHsz 64
#define Rsz 256
#define NKk 4096
#define NSLICE 32

// ---------------- single scratch arena (one symbol, no allocations) ---------
#define OFF_NX    ((size_t)0)
#define OFF_NX2   (OFF_NX   + (size_t)Bsz*Ssz*Dsz)
#define OFF_SC    (OFF_NX2  + (size_t)Bsz*Ssz*Dsz)
#define OFF_MC    (OFF_SC   + (size_t)Bsz*Dsz*Rsz)
#define OFF_E     (OFF_MC   + (size_t)Bsz*Dsz*Rsz)
#define OFF_H     (OFF_E    + (size_t)3*Bsz*Rsz*Dsz)
#define OFF_QM    (OFF_H    + (size_t)Bsz*Ssz*Rsz)
#define OFF_QKV   (OFF_QM   + (size_t)Bsz*Ssz*Rsz)
#define OFF_AO    (OFF_QKV  + (size_t)3*Bsz*Ssz*Dsz)
#define OFF_MS    (OFF_AO   + (size_t)Bsz*Ssz*Dsz)
#define OFF_ACC   (OFF_MS   + (size_t)Bsz*Ssz*NKk)
#define OFF_W     (OFF_ACC  + (size_t)NSLICE*Bsz*5*16)
#define SCRATCH_TOTAL (OFF_W + (size_t)Bsz*5*16)

__device__ float g_scratch[SCRATCH_TOTAL];

// ---------------- helpers ----------------------------------------------------
__device__ __forceinline__ float fexp(float x) {
    x = fmaxf(x, -80.f);
    float z = x * 1.4426950408889634f;
    float r = rintf(z);
    float f = z - r;
    float p =            0.0013333558f;
    p = fmaf(p, f, 0.0096181291f);
    p = fmaf(p, f, 0.0555041087f);
    p = fmaf(p, f, 0.2402264791f);
    p = fmaf(p, f, 0.6931472028f);
    p = fmaf(p, f, 1.0f);
    int e = (int)r;
    return __int_as_float(__float_as_int(p) + (e << 23));
}

__device__ __forceinline__ uint32_t pack_bf16x2(float lo, float hi) {
    __nv_bfloat162 t = __floats2bfloat162_rn(lo, hi);
    uint32_t u;
    memcpy(&u, &t, 4);
    return u;
}

__device__ __forceinline__ void cpasync16(uint32_t dst, const float* src) {
    asm volatile("cp.async.cg.shared.global [%0], [%1], 16;\n" :: "r"(dst), "l"(src));
}

// ---------------- zero router accumulators ----------------------------------
__global__ void zero_kernel(float* p, int n) {
    int i = blockIdx.x*256 + threadIdx.x;
    if (i < n) p[i] = 0.f;
}

// ---------------- LayerNorm + router logits + importance-pooled softmax -----
// (round-7 proven fused version)
__global__ __launch_bounds__(256) void ln_route_kernel(
    const float* __restrict__ X, const float* __restrict__ imp,
    const float* __restrict__ W0, const float* __restrict__ W1,
    const float* __restrict__ W2, const float* __restrict__ W3,
    const float* __restrict__ gamma, const float* __restrict__ beta,
    float* __restrict__ NX, float* __restrict__ accPart,
    int nR, int rbase)
{
    int s = blockIdx.x, b = blockIdx.y, tid = threadIdx.x;
    int lane = tid & 31, wid = tid >> 5;
    const float* xr = X + ((size_t)b*Ssz + s)*Dsz;
    __shared__ float xs[Dsz];
    __shared__ float red[32];
    __shared__ float lg[64];
    float lsum = 0.f, lsq = 0.f;
    for (int i = tid; i < Dsz; i += 256) {
        float v = xr[i]; xs[i] = v; lsum += v; lsq += v*v;
    }
    #pragma unroll
    for (int o = 16; o > 0; o >>= 1) {
        lsum += __shfl_down_sync(0xffffffffu, lsum, o);
        lsq  += __shfl_down_sync(0xffffffffu, lsq,  o);
    }
    if (lane == 0) { red[wid] = lsum; red[8+wid] = lsq; }
    __syncthreads();
    if (tid == 0) {
        float ssum = 0.f, sq = 0.f;
        #pragma unroll
        for (int w = 0; w < 8; w++) { ssum += red[w]; sq += red[8+w]; }
        float mean = ssum / (float)Dsz;
        float var  = sq / (float)Dsz - mean*mean;
        red[16] = mean; red[17] = rsqrtf(var + 1e-5f);
    }
    __syncthreads();
    float mean = red[16], rstd = red[17];
    float* nxr = NX + ((size_t)b*Ssz + s)*Dsz;
    for (int i = tid; i < Dsz; i += 256) {
        float v = (xs[i]-mean)*rstd*gamma[i] + beta[i];
        xs[i] = v; nxr[i] = v;
    }
    __syncthreads();
    for (int e = wid; e < nR*16; e += 8) {
        const float* Wr = (e < 16 ? W0 : (e < 32 ? W1 : (e < 48 ? W2 : W3))) + (size_t)(e & 15)*Dsz;
        float acc = 0.f;
        for (int i = lane; i < Dsz; i += 32) acc += xs[i]*Wr[i];
        #pragma unroll
        for (int o = 16; o > 0; o >>= 1) acc += __shfl_down_sync(0xffffffffu, acc, o);
        if (lane == 0) lg[e] = acc;
    }
    __syncthreads();
    if (tid < nR) {
        float mx = -1e30f;
        #pragma unroll
        for (int e = 0; e < 16; e++) mx = fmaxf(mx, lg[tid*16+e]);
        float ex[16]; float se = 0.f;
        #pragma unroll
        for (int e = 0; e < 16; e++) { ex[e] = __expf(lg[tid*16+e]-mx); se += ex[e]; }
        float wi = imp[(size_t)b*Ssz + s] / se;
        int slice = s & (NSLICE-1);
        float* dst = accPart + ((size_t)(slice*Bsz + b)*5 + rbase + tid)*16;
        #pragma unroll
        for (int e = 0; e < 16; e++) atomicAdd(&dst[e], wi*ex[e]);
    }
}

// ---------------- reduce slices + normalize route weights -------------------
__global__ void finalize_w_kernel(const float* __restrict__ accPart,
                                  float* __restrict__ w, int rbase, int nR)
{
    __shared__ float vals[2*5*16];
    int t = threadIdx.x;
    int tot = Bsz*nR*16;
    if (t < tot) {
        int b = t/(nR*16); int r = (t/16) % nR; int e = t & 15;
        float sum = 0.f;
        for (int sl = 0; sl < NSLICE; sl++)
            sum += accPart[((size_t)(sl*Bsz + b)*5 + rbase + r)*16 + e];
        vals[t] = sum;
    }
    __syncthreads();
    if (t < tot) {
        int b = t/(nR*16); int r = (t/16) % nR;
        float den = 1e-8f;
        #pragma unroll
        for (int j = 0; j < 16; j++) den += vals[(b*nR + r)*16 + j];
        w[((b*5) + rbase + r)*16 + (t & 15)] = vals[t] / den;
    }
}

// ------- weighted pool combine TRANSPOSED: [16,D,R] -> scT [B][R][D] --------
__global__ __launch_bounds__(256) void combine_cT_kernel(
    const float* __restrict__ w, const float* __restrict__ pool,
    float* __restrict__ out, int router)
{
    __shared__ float ws[2][16];
    __shared__ float tile[2][32][33];
    int tid = threadIdx.x;
    if (tid < 32) ws[tid>>4][tid&15] = w[((tid>>4)*5 + router)*16 + (tid&15)];
    __syncthreads();
    int tx = tid & 31, ty = tid >> 5;
    int d0 = blockIdx.x*32, r0 = blockIdx.y*32;
    const size_t X = (size_t)Dsz*Rsz;
    #pragma unroll
    for (int dr = 0; dr < 4; dr++) {
        int dd = ty + dr*8;
        float a0 = 0.f, a1 = 0.f;
        #pragma unroll
        for (int n = 0; n < 16; n++) {
            float p = pool[(size_t)n*X + (size_t)(d0+dd)*Rsz + r0 + tx];
            a0 += ws[0][n]*p; a1 += ws[1][n]*p;
        }
        tile[0][dd][tx] = a0; tile[1][dd][tx] = a1;
    }
    __syncthreads();
    #pragma unroll
    for (int dr = 0; dr < 4; dr++) {
        int rr = ty + dr*8;
        out[(size_t)(r0+rr)*Dsz + d0 + tx]     = tile[0][tx][rr];
        out[X + (size_t)(r0+rr)*Dsz + d0 + tx] = tile[1][tx][rr];
    }
}

// ------- expand combine TRANSPOSED: [16,R,D] -> eT [3*B][D][R] --------------
__global__ __launch_bounds__(256) void combine_eT_kernel(
    const float* __restrict__ w, const float* __restrict__ pool,
    float* __restrict__ out)
{
    __shared__ float ws[6][16];
    __shared__ float tile[6][32][33];
    int tid = threadIdx.x;
    if (tid < 96) {
        int slot = tid>>4, e = tid&15;
        int r3 = slot>>1, b = slot&1;
        ws[slot][e] = w[(b*5 + 1 + r3)*16 + e];
    }
    __syncthreads();
    int tx = tid&31, ty = tid>>5;
    int d0 = blockIdx.x*32, r0 = blockIdx.y*32;
    const size_t X = (size_t)Rsz*Dsz;
    #pragma unroll
    for (int dr = 0; dr < 4; dr++) {
        int rr = ty + dr*8;
        float a[6] = {0.f,0.f,0.f,0.f,0.f,0.f};
        #pragma unroll
        for (int n = 0; n < 16; n++) {
            float p = pool[(size_t)n*X + (size_t)(r0+rr)*Dsz + d0+tx];
            #pragma unroll
            for (int sl = 0; sl < 6; sl++) a[sl] += ws[sl][n]*p;
        }
        #pragma unroll
        for (int sl = 0; sl < 6; sl++) tile[sl][rr][tx] = a[sl];
    }
    __syncthreads();
    #pragma unroll
    for (int dr = 0; dr < 4; dr++) {
        int dd = ty + dr*8;
        #pragma unroll
        for (int sl = 0; sl < 6; sl++)
            out[(size_t)sl*X + (size_t)(d0+dd)*Rsz + r0+tx] = tile[sl][tx][dd];
    }
}

// ---- tf32 tensor-core GEMM (NT), cp.async 2-stage, 32-k chunks, 64KB dyn smem
template<bool RESID>
__global__ __launch_bounds__(256) void tgemm_kernel(
    const float* __restrict__ A, const float* __restrict__ Bm,
    const float* __restrict__ Rsrc, float* __restrict__ C,
    int M, int N, int K, float alpha,
    size_t sA, size_t sB, size_t sC, size_t sR)
{
    extern __shared__ uint32_t dsm[];      // [2][4096] A then [2][4096] B
    A += (size_t)blockIdx.z*sA; Bm += (size_t)blockIdx.z*sB;
    C += (size_t)blockIdx.z*sC; if (RESID) Rsrc += (size_t)blockIdx.z*sR;
    int tid = threadIdx.x, lane = tid&31, warp = tid>>5;
    int wm = warp>>2, wn = warp&3;
    int bm = blockIdx.y<<7, bn = blockIdx.x<<7;

    float c[4][4][4];
    #pragma unroll
    for (int i=0;i<4;i++)
        #pragma unroll
        for(int j=0;j<4;j++)
            #pragma unroll
            for(int f=0;f<4;f++) c[i][j][f]=0.f;

    int row = tid>>1;
    int qb  = (tid&1)*4;
    const float* Aro = A + (size_t)(bm+row)*K;
    const float* Bro = Bm + (size_t)(bn+row)*K;
    int amt = row>>4, arm = row&15;
    int bnt = row>>3, brn = row&7;
    uint32_t aoff = ((amt*4 + (arm>>3))*32 + (arm&7)*4);
    uint32_t boff = ((bnt*2)*32 + brn*4);
    uint32_t smbase = (uint32_t)__cvta_generic_to_shared(dsm);
    uint32_t aAddr = smbase + aoff*4;            // A stage 0
    uint32_t bAddr = smbase + 32768 + boff*4;    // B stage 0

    int nit = K >> 5;
    // prefetch chunk 0 into stage 0
    #pragma unroll
    for (int i = 0; i < 4; i++) {
        int q = qb + i;
        cpasync16(aAddr + (q>>1)*4096 + (q&1)*256, Aro + q*4);
        cpasync16(bAddr + (q>>1)*4096 + (q&1)*128, Bro + q*4);
    }
    asm volatile("cp.async.commit_group;\n" ::: "memory");

    for (int it = 0; it < nit; it++) {
        int st = it & 1;
        if (it + 1 < nit) {
            int k0n = (it+1) << 5;
            uint32_t sb = (uint32_t)(st^1)*16384;
            #pragma unroll
            for (int i = 0; i < 4; i++) {
                int q = qb + i;
                cpasync16(aAddr + sb + (q>>1)*4096 + (q&1)*256, Aro + k0n + q*4);
                cpasync16(bAddr + sb + (q>>1)*4096 + (q&1)*128, Bro + k0n + q*4);
            }
            asm volatile("cp.async.commit_group;\n" ::: "memory");
            asm volatile("cp.async.wait_group 1;\n" ::: "memory");
        } else {
            asm volatile("cp.async.wait_group 0;\n" ::: "memory");
        }
        __syncthreads();
        const uint32_t* Ast = dsm + st*4096;
        const uint32_t* Bst = dsm + 8192 + st*4096;
        #pragma unroll
        for (int k8 = 0; k8 < 4; k8++) {
            uint32_t a[4][4], b[4][2];
            #pragma unroll
            for (int mt = 0; mt < 4; mt++) {
                const uint32_t* p = Ast + k8*1024 + ((wm*4+mt)*4)*32 + lane;
                a[mt][0]=p[0]; a[mt][1]=p[32]; a[mt][2]=p[64]; a[mt][3]=p[96];
            }
            #pragma unroll
            for (int nt = 0; nt < 4; nt++) {
                const uint32_t* p = Bst + k8*1024 + ((wn*4+nt)*2)*32 + lane;
                b[nt][0]=p[0]; b[nt][1]=p[32];
            }
            #pragma unroll
            for (int mt = 0; mt < 4; mt++)
                #pragma unroll
                for (int nt = 0; nt < 4; nt++)
                    asm volatile(
                        "mma.sync.aligned.m16n8k8.row.col.f32.tf32.tf32.f32 "
                        "{%0,%1,%2,%3}, {%4,%5,%6,%7}, {%8,%9}, {%0,%1,%2,%3};"
                        : "+f"(c[mt][nt][0]), "+f"(c[mt][nt][1]),
                          "+f"(c[mt][nt][2]), "+f"(c[mt][nt][3])
                        : "r"(a[mt][0]), "r"(a[mt][1]), "r"(a[mt][2]), "r"(a[mt][3]),
                          "r"(b[nt][0]), "r"(b[nt][1]));
        }
        __syncthreads();
    }
    int g = lane>>2, tg = lane&3;
    #pragma unroll
    for (int mt = 0; mt < 4; mt++) {
        size_t r0 = (size_t)(bm + wm*64 + mt*16 + g);
        size_t r1 = r0 + 8;
        #pragma unroll
        for (int nt = 0; nt < 4; nt++) {
            int col = bn + wn*32 + nt*8 + tg*2;
            float2 v0 = make_float2(alpha*c[mt][nt][0], alpha*c[mt][nt][1]);
            float2 v1 = make_float2(alpha*c[mt][nt][2], alpha*c[mt][nt][3]);
            if (RESID) {
                float2 q0 = *(const float2*)&Rsrc[r0*N + col];
                float2 q1 = *(const float2*)&Rsrc[r1*N + col];
                v0.x += q0.x; v0.y += q0.y; v1.x += q1.x; v1.y += q1.y;
            }
            *(float2*)&C[r0*N + col] = v0;
            *(float2*)&C[r1*N + col] = v1;
        }
    }
}

// ---------------- bf16 tensor-core causal flash attention (dh=64) -----------
__device__ __forceinline__ void mma16816(float* c, const uint32_t* a,
                                         uint32_t b0, uint32_t b1) {
    asm volatile("mma.sync.aligned.m16n8k16.row.col.f32.bf16.bf16.f32 "
        "{%0,%1,%2,%3}, {%4,%5,%6,%7}, {%8,%9}, {%0,%1,%2,%3};"
        : "+f"(c[0]),"+f"(c[1]),"+f"(c[2]),"+f"(c[3])
        : "r"(a[0]),"r"(a[1]),"r"(a[2]),"r"(a[3]), "r"(b0),"r"(b1));
}

__global__ __launch_bounds__(128) void flash_mma_kernel(
    const float* __restrict__ Q, const float* __restrict__ Kt,
    const float* __restrict__ V, float* __restrict__ O)
{
    __shared__ __nv_bfloat16 Ks[64][72];
    __shared__ __nv_bfloat16 Vs[64][72];
    int qt = blockIdx.x, h = blockIdx.y, b = blockIdx.z;
    int tid = threadIdx.x, lane = tid&31, w = tid>>5;
    int g = lane>>2, tg = lane&3;
    const size_t base = ((size_t)b*Ssz)*Dsz + h*DHsz;
    int qb = qt*64;
    int frow = tid>>1, fd0 = (tid&1)*32;

    {
        const float* src = Q + base + (size_t)(qb+frow)*Dsz + fd0;
        #pragma unroll
        for (int j = 0; j < 8; j++) {
            float4 v = *(const float4*)(src + j*4);
            *(__nv_bfloat162*)&Ks[frow][fd0+j*4]   = __floats2bfloat162_rn(v.x*0.125f, v.y*0.125f);
            *(__nv_bfloat162*)&Ks[frow][fd0+j*4+2] = __floats2bfloat162_rn(v.z*0.125f, v.w*0.125f);
        }
    }
    __syncthreads();
    uint32_t qa[4][4];
    #pragma unroll
    for (int ks = 0; ks < 4; ks++) {
        qa[ks][0] = *(const uint32_t*)&Ks[w*16+g  ][ks*16+2*tg];
        qa[ks][1] = *(const uint32_t*)&Ks[w*16+g+8][ks*16+2*tg];
        qa[ks][2] = *(const uint32_t*)&Ks[w*16+g  ][ks*16+2*tg+8];
        qa[ks][3] = *(const uint32_t*)&Ks[w*16+g+8][ks*16+2*tg+8];
    }

    float o[8][4];
    #pragma unroll
    for (int nt = 0; nt < 8; nt++)
        o[nt][0]=o[nt][1]=o[nt][2]=o[nt][3]=0.f;
    float m0=-1e30f, m1=-1e30f, l0=0.f, l1=0.f;
    int row0 = qb + w*16 + g;

    for (int kt = 0; kt <= qt; kt++) {
        int k0 = kt*64;
        __syncthreads();
        {
            const float* ksrc = Kt + base + (size_t)(k0+frow)*Dsz + fd0;
            const float* vsrc = V  + base + (size_t)(k0+frow)*Dsz + fd0;
            #pragma unroll
            for (int j = 0; j < 8; j++) {
                float4 kv = *(const float4*)(ksrc + j*4);
                *(__nv_bfloat162*)&Ks[frow][fd0+j*4]   = __floats2bfloat162_rn(kv.x, kv.y);
                *(__nv_bfloat162*)&Ks[frow][fd0+j*4+2] = __floats2bfloat162_rn(kv.z, kv.w);
                float4 vv = *(const float4*)(vsrc + j*4);
                Vs[fd0+j*4  ][frow] = __float2bfloat16(vv.x);
                Vs[fd0+j*4+1][frow] = __float2bfloat16(vv.y);
                Vs[fd0+j*4+2][frow] = __float2bfloat16(vv.z);
                Vs[fd0+j*4+3][frow] = __float2bfloat16(vv.w);
            }
        }
        __syncthreads();

        float sc[8][4];
        #pragma unroll
        for (int nt = 0; nt < 8; nt++) {
            sc[nt][0]=sc[nt][1]=sc[nt][2]=sc[nt][3]=0.f;
            #pragma unroll
            for (int ks = 0; ks < 4; ks++) {
                uint32_t kb0 = *(const uint32_t*)&Ks[nt*8+g][ks*16+2*tg];
                uint32_t kb1 = *(const uint32_t*)&Ks[nt*8+g][ks*16+2*tg+8];
                mma16816(sc[nt], qa[ks], kb0, kb1);
            }
        }
        if (kt == qt) {
            #pragma unroll
            for (int nt = 0; nt < 8; nt++) {
                int col = k0 + nt*8 + 2*tg;
                if (col   > row0)   sc[nt][0] = -1e30f;
                if (col+1 > row0)   sc[nt][1] = -1e30f;
                if (col   > row0+8) sc[nt][2] = -1e30f;
                if (col+1 > row0+8) sc[nt][3] = -1e30f;
            }
        }
        float mx0 = -1e30f, mx1 = -1e30f;
        #pragma unroll
        for (int nt = 0; nt < 8; nt++) {
            mx0 = fmaxf(mx0, fmaxf(sc[nt][0], sc[nt][1]));
            mx1 = fmaxf(mx1, fmaxf(sc[nt][2], sc[nt][3]));
        }
        mx0 = fmaxf(mx0, __shfl_xor_sync(0xffffffffu, mx0, 1));
        mx0 = fmaxf(mx0, __shfl_xor_sync(0xffffffffu, mx0, 2));
        mx1 = fmaxf(mx1, __shfl_xor_sync(0xffffffffu, mx1, 1));
        mx1 = fmaxf(mx1, __shfl_xor_sync(0xffffffffu, mx1, 2));
        float nm0 = fmaxf(m0, mx0), nm1 = fmaxf(m1, mx1);
        float c0 = fexp(m0 - nm0), c1 = fexp(m1 - nm1);
        m0 = nm0; m1 = nm1;

        uint32_t pa[4][4];
        float s0 = 0.f, s1 = 0.f;
        #pragma unroll
        for (int nt = 0; nt < 8; nt++) {
            float e0 = fexp(sc[nt][0]-m0), e1 = fexp(sc[nt][1]-m0);
            float e2 = fexp(sc[nt][2]-m1), e3 = fexp(sc[nt][3]-m1);
            s0 += e0+e1; s1 += e2+e3;
            int ks = nt>>1, hi = (nt&1)*2;
            pa[ks][hi+0] = pack_bf16x2(e0, e1);
            pa[ks][hi+1] = pack_bf16x2(e2, e3);
        }
        s0 += __shfl_xor_sync(0xffffffffu, s0, 1);
        s0 += __shfl_xor_sync(0xffffffffu, s0, 2);
        s1 += __shfl_xor_sync(0xffffffffu, s1, 1);
        s1 += __shfl_xor_sync(0xffffffffu, s1, 2);
        l0 = l0*c0 + s0; l1 = l1*c1 + s1;

        #pragma unroll
        for (int nt = 0; nt < 8; nt++) {
            o[nt][0]*=c0; o[nt][1]*=c0; o[nt][2]*=c1; o[nt][3]*=c1;
            #pragma unroll
            for (int ks = 0; ks < 4; ks++) {
                uint32_t vb0 = *(const uint32_t*)&Vs[nt*8+g][ks*16+2*tg];
                uint32_t vb1 = *(const uint32_t*)&Vs[nt*8+g][ks*16+2*tg+8];
                mma16816(o[nt], pa[ks], vb0, vb1);
            }
        }
    }
    float i0 = 1.f/l0, i1 = 1.f/l1;
    #pragma unroll
    for (int nt = 0; nt < 8; nt++) {
        float2 v0 = make_float2(o[nt][0]*i0, o[nt][1]*i0);
        float2 v1 = make_float2(o[nt][2]*i1, o[nt][3]*i1);
        *(float2*)&O[base + (size_t)row0*Dsz + nt*8 + 2*tg]     = v0;
        *(float2*)&O[base + (size_t)(row0+8)*Dsz + nt*8 + 2*tg] = v1;
    }
}

// ---------------- top-8 + softmax + knowledge gather + residual add ---------
__global__ __launch_bounds__(256) void topk_mem_kernel(
    const float* __restrict__ MS, const float* __restrict__ KV,
    float* __restrict__ OUT)
{
    int s = blockIdx.x, b = blockIdx.y, tid = threadIdx.x;
    __shared__ float sc[NKk];
    __shared__ float rv[256];
    __shared__ int   ri[256];
    __shared__ float topv[8];
    __shared__ int   topi[8];
    __shared__ float tw[8];
    const float* row = MS + ((size_t)b*Ssz + s)*NKk;
    for (int i = tid; i < NKk; i += 256) sc[i] = row[i];
    __syncthreads();
    for (int it = 0; it < 8; it++) {
        float bv = -1e30f; int bi = NKk;
        for (int i = tid; i < NKk; i += 256) {
            float v = sc[i];
            if (v > bv) { bv = v; bi = i; }
        }
        rv[tid] = bv; ri[tid] = bi;
        __syncthreads();
        for (int off = 128; off > 0; off >>= 1) {
            if (tid < off) {
                if (rv[tid+off] > rv[tid] ||
                    (rv[tid+off] == rv[tid] && ri[tid+off] < ri[tid])) {
                    rv[tid] = rv[tid+off]; ri[tid] = ri[tid+off];
                }
            }
            __syncthreads();
        }
        if (tid == 0) { topv[it] = rv[0]; topi[it] = ri[0]; sc[ri[0]] = -1e30f; }
        __syncthreads();
    }
    if (tid == 0) {
        float mx = topv[0]; float se = 0.f;
        #pragma unroll
        for (int k = 0; k < 8; k++) { tw[k] = __expf(topv[k]-mx); se += tw[k]; }
        float inv = 1.f/se;
        #pragma unroll
        for (int k = 0; k < 8; k++) tw[k] *= inv;
    }
    __syncthreads();
    float w0 = tw[0], w1 = tw[1], w2 = tw[2], w3 = tw[3];
    float w4 = tw[4], w5 = tw[5], w6 = tw[6], w7 = tw[7];
    size_t i0 = (size_t)topi[0]*Dsz, i1 = (size_t)topi[1]*Dsz;
    size_t i2 = (size_t)topi[2]*Dsz, i3 = (size_t)topi[3]*Dsz;
    size_t i4 = (size_t)topi[4]*Dsz, i5 = (size_t)topi[5]*Dsz;
    size_t i6 = (size_t)topi[6]*Dsz, i7 = (size_t)topi[7]*Dsz;
    float* o = OUT + ((size_t)b*Ssz + s)*Dsz;
    for (int d = tid; d < Dsz; d += 256) {
        float a = o[d];
        a = fmaf(w0, KV[i0+d], a); a = fmaf(w1, KV[i1+d], a);
        a = fmaf(w2, KV[i2+d], a); a = fmaf(w3, KV[i3+d], a);
        a = fmaf(w4, KV[i4+d], a); a = fmaf(w5, KV[i5+d], a);
        a = fmaf(w6, KV[i6+d], a); a = fmaf(w7, KV[i7+d], a);
        o[d] = a;
    }
}

// ---------------- launch ----------------------------------------------------
extern "C" void kernel_launch(void* const* d_in, const int* in_sizes, int n_in,
                              void* d_out, int out_size)
{
    const float* x    = (const float*)d_in[0];
    const float* imp  = (const float*)d_in[1];
    const float* Wc   = (const float*)d_in[2];
    const float* WQ   = (const float*)d_in[3];
    const float* WK   = (const float*)d_in[4];
    const float* WV   = (const float*)d_in[5];
    const float* Wm   = (const float*)d_in[6];
    const float* cn   = (const float*)d_in[7];
    const float* pool = (const float*)d_in[8];
    const float* kK   = (const float*)d_in[9];
    const float* kV   = (const float*)d_in[10];
    const float* WO   = (const float*)d_in[11];
    const float* g1   = (const float*)d_in[12];
    const float* b1   = (const float*)d_in[13];
    const float* g2   = (const float*)d_in[14];
    const float* b2   = (const float*)d_in[15];
    float* out = (float*)d_out;

    static float* base = nullptr;
    if (!base) {
        cudaGetSymbolAddress((void**)&base, g_scratch);
        cudaFuncSetAttribute(tgemm_kernel<false>,
            cudaFuncAttributeMaxDynamicSharedMemorySize, 65536);
        cudaFuncSetAttribute(tgemm_kernel<true>,
            cudaFuncAttributeMaxDynamicSharedMemorySize, 65536);
    }

    float* nx   = base + OFF_NX;
    float* nx2  = base + OFF_NX2;
    float* scp  = base + OFF_SC;
    float* mcp  = base + OFF_MC;
    float* ep   = base + OFF_E;
    float* hp   = base + OFF_H;
    float* qmp  = base + OFF_QM;
    float* qkvp = base + OFF_QKV;
    float* aop  = base + OFF_AO;
    float* msp  = base + OFF_MS;
    float* accP = base + OFF_ACC;
    float* wptr = base + OFF_W;

    const size_t SD = (size_t)Ssz*Dsz;
    const size_t SR = (size_t)Ssz*Rsz;
    const size_t RD = (size_t)Rsz*Dsz;
    const size_t BSD = (size_t)Bsz*Ssz*Dsz;
    const size_t SNK = (size_t)Ssz*NKk;
    const int DSM = 65536;

    zero_kernel<<<(NSLICE*Bsz*5*16 + 255)/256, 256>>>(accP, NSLICE*Bsz*5*16);
    ln_route_kernel<<<dim3(Ssz, Bsz), 256>>>(x, imp, Wc, WQ, WK, WV, g1, b1,
                                             nx, accP, 4, 0);
    finalize_w_kernel<<<1, 256>>>(accP, wptr, 0, 4);
    combine_cT_kernel<<<dim3(Dsz/32, Rsz/32), 256>>>(wptr, cn, scp, 0);
    combine_eT_kernel<<<dim3(Dsz/32, Rsz/32), 256>>>(wptr, pool, ep);
    tgemm_kernel<false><<<dim3(Rsz/128, Ssz/128, Bsz), 256, DSM>>>(nx, scp,
        nullptr, hp, Ssz, Rsz, Dsz, 1.f, SD, RD, SR, 0);
    for (int r3 = 0; r3 < 3; r3++)
        tgemm_kernel<false><<<dim3(Dsz/128, Ssz/128, Bsz), 256, DSM>>>(hp,
            ep + (size_t)r3*Bsz*RD, nullptr, qkvp + (size_t)r3*BSD,
            Ssz, Dsz, Rsz, 1.f, SR, RD, SD, 0);
    flash_mma_kernel<<<dim3(Ssz/64, Hsz, Bsz), 128>>>(qkvp, qkvp + BSD,
                                                      qkvp + 2*BSD, aop);
    tgemm_kernel<true><<<dim3(Dsz/128, Ssz/128, Bsz), 256, DSM>>>(aop, WO, x, out,
        Ssz, Dsz, Dsz, 1.f, SD, 0, SD, SD);
    ln_route_kernel<<<dim3(Ssz, Bsz), 256>>>(out, imp, Wm, Wm, Wm, Wm, g2, b2,
                                             nx2, accP, 1, 4);
    finalize_w_kernel<<<1, 256>>>(accP, wptr, 4, 1);
    combine_cT_kernel<<<dim3(Dsz/32, Rsz/32), 256>>>(wptr, cn, mcp, 4);
    tgemm_kernel<false><<<dim3(Rsz/128, Ssz/128, Bsz), 256, DSM>>>(nx2, mcp,
        nullptr, qmp, Ssz, Rsz, Dsz, 1.f, SD, RD, SR, 0);
    tgemm_kernel<false><<<dim3(NKk/128, Ssz/128, Bsz), 256, DSM>>>(qmp, kK,
        nullptr, msp, Ssz, NKk, Rsz, 0.0625f, SR, 0, SNK, 0);
    topk_mem_kernel<<<dim3(Ssz, Bsz), 256>>>(msp, kV, out);
}

// round 15
// speedup vs baseline: 1.1307x; 1.1307x over previous
#include <cuda_runtime.h>
#include <cuda_bf16.h>
#include <math.h>
#include <stdint.h>

#define Bsz 2
#define Ssz 2048
#define Dsz 1024
#define Hsz 16
#define DHsz 64
#define Rsz 256
#define NKk 4096
#define NSLICE 32

// ---------------- single scratch arena (one symbol, no allocations) ---------
#define OFF_NX    ((size_t)0)
#define OFF_NX2   (OFF_NX   + (size_t)Bsz*Ssz*Dsz)
#define OFF_SC    (OFF_NX2  + (size_t)Bsz*Ssz*Dsz)
#define OFF_MC    (OFF_SC   + (size_t)Bsz*Dsz*Rsz)
#define OFF_E     (OFF_MC   + (size_t)Bsz*Dsz*Rsz)
#define OFF_H     (OFF_E    + (size_t)3*Bsz*Rsz*Dsz)
#define OFF_QM    (OFF_H    + (size_t)Bsz*Ssz*Rsz)
#define OFF_QKV   (OFF_QM   + (size_t)Bsz*Ssz*Rsz)
#define OFF_AO    (OFF_QKV  + (size_t)3*Bsz*Ssz*Dsz)
#define OFF_MS    (OFF_AO   + (size_t)Bsz*Ssz*Dsz)
#define OFF_ACC   (OFF_MS   + (size_t)Bsz*Ssz*NKk)
#define OFF_W     (OFF_ACC  + (size_t)NSLICE*Bsz*5*16)
#define SCRATCH_TOTAL (OFF_W + (size_t)Bsz*5*16)

__device__ float g_scratch[SCRATCH_TOTAL];

// ---------------- helpers ----------------------------------------------------
__device__ __forceinline__ float fexp(float x) {
    x = fmaxf(x, -80.f);
    float z = x * 1.4426950408889634f;
    float r = rintf(z);
    float f = z - r;
    float p =            0.0013333558f;
    p = fmaf(p, f, 0.0096181291f);
    p = fmaf(p, f, 0.0555041087f);
    p = fmaf(p, f, 0.2402264791f);
    p = fmaf(p, f, 0.6931472028f);
    p = fmaf(p, f, 1.0f);
    int e = (int)r;
    return __int_as_float(__float_as_int(p) + (e << 23));
}

__device__ __forceinline__ uint32_t pack_bf16x2(float lo, float hi) {
    __nv_bfloat162 t = __floats2bfloat162_rn(lo, hi);
    uint32_t u;
    memcpy(&u, &t, 4);
    return u;
}

// ---------------- zero router accumulators ----------------------------------
__global__ void zero_kernel(float* p, int n) {
    int i = blockIdx.x*256 + threadIdx.x;
    if (i < n) p[i] = 0.f;
}

// ---------------- LayerNorm + router logits + importance-pooled softmax -----
__global__ __launch_bounds__(256) void ln_route_kernel(
    const float* __restrict__ X, const float* __restrict__ imp,
    const float* __restrict__ W0, const float* __restrict__ W1,
    const float* __restrict__ W2, const float* __restrict__ W3,
    const float* __restrict__ gamma, const float* __restrict__ beta,
    float* __restrict__ NX, float* __restrict__ accPart,
    int nR, int rbase)
{
    int s = blockIdx.x, b = blockIdx.y, tid = threadIdx.x;
    int lane = tid & 31, wid = tid >> 5;
    const float* xr = X + ((size_t)b*Ssz + s)*Dsz;
    __shared__ float xs[Dsz];
    __shared__ float red[32];
    __shared__ float lg[64];
    float lsum = 0.f, lsq = 0.f;
    for (int i = tid; i < Dsz; i += 256) {
        float v = xr[i]; xs[i] = v; lsum += v; lsq += v*v;
    }
    #pragma unroll
    for (int o = 16; o > 0; o >>= 1) {
        lsum += __shfl_down_sync(0xffffffffu, lsum, o);
        lsq  += __shfl_down_sync(0xffffffffu, lsq,  o);
    }
    if (lane == 0) { red[wid] = lsum; red[8+wid] = lsq; }
    __syncthreads();
    if (tid == 0) {
        float ssum = 0.f, sq = 0.f;
        #pragma unroll
        for (int w = 0; w < 8; w++) { ssum += red[w]; sq += red[8+w]; }
        float mean = ssum / (float)Dsz;
        float var  = sq / (float)Dsz - mean*mean;
        red[16] = mean; red[17] = rsqrtf(var + 1e-5f);
    }
    __syncthreads();
    float mean = red[16], rstd = red[17];
    float* nxr = NX + ((size_t)b*Ssz + s)*Dsz;
    for (int i = tid; i < Dsz; i += 256) {
        float v = (xs[i]-mean)*rstd*gamma[i] + beta[i];
        xs[i] = v; nxr[i] = v;
    }
    __syncthreads();
    for (int e = wid; e < nR*16; e += 8) {
        const float* Wr = (e < 16 ? W0 : (e < 32 ? W1 : (e < 48 ? W2 : W3))) + (size_t)(e & 15)*Dsz;
        float acc = 0.f;
        for (int i = lane; i < Dsz; i += 32) acc += xs[i]*Wr[i];
        #pragma unroll
        for (int o = 16; o > 0; o >>= 1) acc += __shfl_down_sync(0xffffffffu, acc, o);
        if (lane == 0) lg[e] = acc;
    }
    __syncthreads();
    if (tid < nR) {
        float mx = -1e30f;
        #pragma unroll
        for (int e = 0; e < 16; e++) mx = fmaxf(mx, lg[tid*16+e]);
        float ex[16]; float se = 0.f;
        #pragma unroll
        for (int e = 0; e < 16; e++) { ex[e] = __expf(lg[tid*16+e]-mx); se += ex[e]; }
        float wi = imp[(size_t)b*Ssz + s] / se;
        int slice = s & (NSLICE-1);
        float* dst = accPart + ((size_t)(slice*Bsz + b)*5 + rbase + tid)*16;
        #pragma unroll
        for (int e = 0; e < 16; e++) atomicAdd(&dst[e], wi*ex[e]);
    }
}

// ---------------- reduce slices + normalize route weights -------------------
__global__ void finalize_w_kernel(const float* __restrict__ accPart,
                                  float* __restrict__ w, int rbase, int nR)
{
    __shared__ float vals[2*5*16];
    int t = threadIdx.x;
    int tot = Bsz*nR*16;
    if (t < tot) {
        int b = t/(nR*16); int r = (t/16) % nR; int e = t & 15;
        float sum = 0.f;
        for (int sl = 0; sl < NSLICE; sl++)
            sum += accPart[((size_t)(sl*Bsz + b)*5 + rbase + r)*16 + e];
        vals[t] = sum;
    }
    __syncthreads();
    if (t < tot) {
        int b = t/(nR*16); int r = (t/16) % nR;
        float den = 1e-8f;
        #pragma unroll
        for (int j = 0; j < 16; j++) den += vals[(b*nR + r)*16 + j];
        w[((b*5) + rbase + r)*16 + (t & 15)] = vals[t] / den;
    }
}

// ------- weighted pool combine TRANSPOSED: [16,D,R] -> scT [B][R][D] --------
__global__ __launch_bounds__(256) void combine_cT_kernel(
    const float* __restrict__ w, const float* __restrict__ pool,
    float* __restrict__ out, int router)
{
    __shared__ float ws[2][16];
    __shared__ float tile[2][32][33];
    int tid = threadIdx.x;
    if (tid < 32) ws[tid>>4][tid&15] = w[((tid>>4)*5 + router)*16 + (tid&15)];
    __syncthreads();
    int tx = tid & 31, ty = tid >> 5;
    int d0 = blockIdx.x*32, r0 = blockIdx.y*32;
    const size_t X = (size_t)Dsz*Rsz;
    #pragma unroll
    for (int dr = 0; dr < 4; dr++) {
        int dd = ty + dr*8;
        float a0 = 0.f, a1 = 0.f;
        #pragma unroll
        for (int n = 0; n < 16; n++) {
            float p = pool[(size_t)n*X + (size_t)(d0+dd)*Rsz + r0 + tx];
            a0 += ws[0][n]*p; a1 += ws[1][n]*p;
        }
        tile[0][dd][tx] = a0; tile[1][dd][tx] = a1;
    }
    __syncthreads();
    #pragma unroll
    for (int dr = 0; dr < 4; dr++) {
        int rr = ty + dr*8;
        out[(size_t)(r0+rr)*Dsz + d0 + tx]     = tile[0][tx][rr];
        out[X + (size_t)(r0+rr)*Dsz + d0 + tx] = tile[1][tx][rr];
    }
}

// ------- expand combine TRANSPOSED: [16,R,D] -> eT [3*B][D][R] --------------
__global__ __launch_bounds__(256) void combine_eT_kernel(
    const float* __restrict__ w, const float* __restrict__ pool,
    float* __restrict__ out)
{
    __shared__ float ws[6][16];
    __shared__ float tile[6][32][33];
    int tid = threadIdx.x;
    if (tid < 96) {
        int slot = tid>>4, e = tid&15;
        int r3 = slot>>1, b = slot&1;
        ws[slot][e] = w[(b*5 + 1 + r3)*16 + e];
    }
    __syncthreads();
    int tx = tid&31, ty = tid>>5;
    int d0 = blockIdx.x*32, r0 = blockIdx.y*32;
    const size_t X = (size_t)Rsz*Dsz;
    #pragma unroll
    for (int dr = 0; dr < 4; dr++) {
        int rr = ty + dr*8;
        float a[6] = {0.f,0.f,0.f,0.f,0.f,0.f};
        #pragma unroll
        for (int n = 0; n < 16; n++) {
            float p = pool[(size_t)n*X + (size_t)(r0+rr)*Dsz + d0+tx];
            #pragma unroll
            for (int sl = 0; sl < 6; sl++) a[sl] += ws[sl][n]*p;
        }
        #pragma unroll
        for (int sl = 0; sl < 6; sl++) tile[sl][rr][tx] = a[sl];
    }
    __syncthreads();
    #pragma unroll
    for (int dr = 0; dr < 4; dr++) {
        int dd = ty + dr*8;
        #pragma unroll
        for (int sl = 0; sl < 6; sl++)
            out[(size_t)sl*X + (size_t)(d0+dd)*Rsz + r0+tx] = tile[sl][tx][dd];
    }
}

// ---------------- tf32 tensor-core GEMM (NT): C = alpha*A[M,K] x B[N,K]^T ---
// (round-7 proven version: LDG + cvt.rna staging, 32-k chunks, 32KB smem)
template<bool RESID>
__global__ __launch_bounds__(256) void tgemm_kernel(
    const float* __restrict__ A, const float* __restrict__ Bm,
    const float* __restrict__ Rsrc, float* __restrict__ C,
    int M, int N, int K, float alpha,
    size_t sA, size_t sB, size_t sC, size_t sR)
{
    __shared__ uint32_t As[4*8*4*32];
    __shared__ uint32_t Bs[4*16*2*32];
    A += (size_t)blockIdx.z*sA; Bm += (size_t)blockIdx.z*sB;
    C += (size_t)blockIdx.z*sC; if (RESID) Rsrc += (size_t)blockIdx.z*sR;
    int tid = threadIdx.x, lane = tid&31, warp = tid>>5;
    int wm = warp>>2, wn = warp&3;
    int bm = blockIdx.y<<7, bn = blockIdx.x<<7;

    float c[4][4][4];
    #pragma unroll
    for (int i=0;i<4;i++)
        #pragma unroll
        for(int j=0;j<4;j++)
            #pragma unroll
            for(int f=0;f<4;f++) c[i][j][f]=0.f;

    int row = tid>>1;
    int qb  = (tid&1)*4;
    const float* Aro = A + (size_t)(bm+row)*K;
    const float* Bro = Bm + (size_t)(bn+row)*K;
    int amt = row>>4, arm = row&15;
    int bnt = row>>3, brn = row&7;
    uint32_t* Abase = As + ((amt*4 + (arm>>3))*32) + (arm&7)*4;
    uint32_t* Bbase = Bs + (bnt*2)*32 + brn*4;

    for (int k0 = 0; k0 < K; k0 += 32) {
        #pragma unroll
        for (int i = 0; i < 4; i++) {
            int q = qb + i;
            float4 v = *(const float4*)(Aro + k0 + q*4);
            uint4 u;
            asm("cvt.rna.tf32.f32 %0,%1;":"=r"(u.x):"f"(v.x));
            asm("cvt.rna.tf32.f32 %0,%1;":"=r"(u.y):"f"(v.y));
            asm("cvt.rna.tf32.f32 %0,%1;":"=r"(u.z):"f"(v.z));
            asm("cvt.rna.tf32.f32 %0,%1;":"=r"(u.w):"f"(v.w));
            *(uint4*)(Abase + (q>>1)*1024 + (q&1)*64) = u;
        }
        #pragma unroll
        for (int i = 0; i < 4; i++) {
            int q = qb + i;
            float4 v = *(const float4*)(Bro + k0 + q*4);
            uint4 u;
            asm("cvt.rna.tf32.f32 %0,%1;":"=r"(u.x):"f"(v.x));
            asm("cvt.rna.tf32.f32 %0,%1;":"=r"(u.y):"f"(v.y));
            asm("cvt.rna.tf32.f32 %0,%1;":"=r"(u.z):"f"(v.z));
            asm("cvt.rna.tf32.f32 %0,%1;":"=r"(u.w):"f"(v.w));
            *(uint4*)(Bbase + (q>>1)*1024 + (q&1)*32) = u;
        }
        __syncthreads();
        #pragma unroll
        for (int k8 = 0; k8 < 4; k8++) {
            uint32_t a[4][4], b[4][2];
            #pragma unroll
            for (int mt = 0; mt < 4; mt++) {
                const uint32_t* p = As + k8*1024 + ((wm*4+mt)*4)*32 + lane;
                a[mt][0]=p[0]; a[mt][1]=p[32]; a[mt][2]=p[64]; a[mt][3]=p[96];
            }
            #pragma unroll
            for (int nt = 0; nt < 4; nt++) {
                const uint32_t* p = Bs + k8*1024 + ((wn*4+nt)*2)*32 + lane;
                b[nt][0]=p[0]; b[nt][1]=p[32];
            }
            #pragma unroll
            for (int mt = 0; mt < 4; mt++)
                #pragma unroll
                for (int nt = 0; nt < 4; nt++)
                    asm volatile(
                        "mma.sync.aligned.m16n8k8.row.col.f32.tf32.tf32.f32 "
                        "{%0,%1,%2,%3}, {%4,%5,%6,%7}, {%8,%9}, {%0,%1,%2,%3};"
                        : "+f"(c[mt][nt][0]), "+f"(c[mt][nt][1]),
                          "+f"(c[mt][nt][2]), "+f"(c[mt][nt][3])
                        : "r"(a[mt][0]), "r"(a[mt][1]), "r"(a[mt][2]), "r"(a[mt][3]),
                          "r"(b[nt][0]), "r"(b[nt][1]));
        }
        __syncthreads();
    }
    int g = lane>>2, tg = lane&3;
    #pragma unroll
    for (int mt = 0; mt < 4; mt++) {
        size_t r0 = (size_t)(bm + wm*64 + mt*16 + g);
        size_t r1 = r0 + 8;
        #pragma unroll
        for (int nt = 0; nt < 4; nt++) {
            int col = bn + wn*32 + nt*8 + tg*2;
            float2 v0 = make_float2(alpha*c[mt][nt][0], alpha*c[mt][nt][1]);
            float2 v1 = make_float2(alpha*c[mt][nt][2], alpha*c[mt][nt][3]);
            if (RESID) {
                float2 q0 = *(const float2*)&Rsrc[r0*N + col];
                float2 q1 = *(const float2*)&Rsrc[r1*N + col];
                v0.x += q0.x; v0.y += q0.y; v1.x += q1.x; v1.y += q1.y;
            }
            *(float2*)&C[r0*N + col] = v0;
            *(float2*)&C[r1*N + col] = v1;
        }
    }
}

// ---------------- bf16 tensor-core causal flash attention (dh=64) -----------
// 256 threads = 8 warps; CTA handles 128 q-rows; 64-key tiles shared by all.
__device__ __forceinline__ void mma16816(float* c, const uint32_t* a,
                                         uint32_t b0, uint32_t b1) {
    asm volatile("mma.sync.aligned.m16n8k16.row.col.f32.bf16.bf16.f32 "
        "{%0,%1,%2,%3}, {%4,%5,%6,%7}, {%8,%9}, {%0,%1,%2,%3};"
        : "+f"(c[0]),"+f"(c[1]),"+f"(c[2]),"+f"(c[3])
        : "r"(a[0]),"r"(a[1]),"r"(a[2]),"r"(a[3]), "r"(b0),"r"(b1));
}

__global__ __launch_bounds__(256) void flash_mma_kernel(
    const float* __restrict__ Q, const float* __restrict__ Kt,
    const float* __restrict__ V, float* __restrict__ O)
{
    __shared__ __nv_bfloat16 Ks[64][72];   // K tile [key][d]  (also Q staging)
    __shared__ __nv_bfloat16 Vs[64][72];   // V tile transposed [d][key]
    int qt = blockIdx.x, h = blockIdx.y, b = blockIdx.z;
    int tid = threadIdx.x, lane = tid&31, w = tid>>5;
    int g = lane>>2, tg = lane&3;
    const size_t base = ((size_t)b*Ssz)*Dsz + h*DHsz;
    int qb = qt*128;
    int frow = tid>>2, fd0 = (tid&3)*16;   // fill: 16 floats (4x float4) per thread
    int lrow = (w&3)*16 + g;               // staging row for this warp's fragments
    int row0 = qb + w*16 + g;              // this thread's global q rows: row0, row0+8

    uint32_t qa[4][4];
    // stage Q rows qb..qb+63 (scaled 1/8), warps 0-3 extract
    {
        const float* src = Q + base + (size_t)(qb+frow)*Dsz + fd0;
        #pragma unroll
        for (int j = 0; j < 4; j++) {
            float4 v = *(const float4*)(src + j*4);
            *(__nv_bfloat162*)&Ks[frow][fd0+j*4]   = __floats2bfloat162_rn(v.x*0.125f, v.y*0.125f);
            *(__nv_bfloat162*)&Ks[frow][fd0+j*4+2] = __floats2bfloat162_rn(v.z*0.125f, v.w*0.125f);
        }
    }
    __syncthreads();
    if (w < 4) {
        #pragma unroll
        for (int ks = 0; ks < 4; ks++) {
            qa[ks][0] = *(const uint32_t*)&Ks[lrow  ][ks*16+2*tg];
            qa[ks][1] = *(const uint32_t*)&Ks[lrow+8][ks*16+2*tg];
            qa[ks][2] = *(const uint32_t*)&Ks[lrow  ][ks*16+2*tg+8];
            qa[ks][3] = *(const uint32_t*)&Ks[lrow+8][ks*16+2*tg+8];
        }
    }
    __syncthreads();
    // stage Q rows qb+64..qb+127, warps 4-7 extract
    {
        const float* src = Q + base + (size_t)(qb+64+frow)*Dsz + fd0;
        #pragma unroll
        for (int j = 0; j < 4; j++) {
            float4 v = *(const float4*)(src + j*4);
            *(__nv_bfloat162*)&Ks[frow][fd0+j*4]   = __floats2bfloat162_rn(v.x*0.125f, v.y*0.125f);
            *(__nv_bfloat162*)&Ks[frow][fd0+j*4+2] = __floats2bfloat162_rn(v.z*0.125f, v.w*0.125f);
        }
    }
    __syncthreads();
    if (w >= 4) {
        #pragma unroll
        for (int ks = 0; ks < 4; ks++) {
            qa[ks][0] = *(const uint32_t*)&Ks[lrow  ][ks*16+2*tg];
            qa[ks][1] = *(const uint32_t*)&Ks[lrow+8][ks*16+2*tg];
            qa[ks][2] = *(const uint32_t*)&Ks[lrow  ][ks*16+2*tg+8];
            qa[ks][3] = *(const uint32_t*)&Ks[lrow+8][ks*16+2*tg+8];
        }
    }

    float o[8][4];
    #pragma unroll
    for (int nt = 0; nt < 8; nt++)
        o[nt][0]=o[nt][1]=o[nt][2]=o[nt][3]=0.f;
    float m0=-1e30f, m1=-1e30f, l0=0.f, l1=0.f;

    int ntiles = 2*qt + 2;
    for (int kt = 0; kt < ntiles; kt++) {
        int k0 = kt*64;
        __syncthreads();
        {   // fill K tile [key][d] and V tile transposed [d][key]
            const float* ksrc = Kt + base + (size_t)(k0+frow)*Dsz + fd0;
            const float* vsrc = V  + base + (size_t)(k0+frow)*Dsz + fd0;
            #pragma unroll
            for (int j = 0; j < 4; j++) {
                float4 kv = *(const float4*)(ksrc + j*4);
                *(__nv_bfloat162*)&Ks[frow][fd0+j*4]   = __floats2bfloat162_rn(kv.x, kv.y);
                *(__nv_bfloat162*)&Ks[frow][fd0+j*4+2] = __floats2bfloat162_rn(kv.z, kv.w);
                float4 vv = *(const float4*)(vsrc + j*4);
                Vs[fd0+j*4  ][frow] = __float2bfloat16(vv.x);
                Vs[fd0+j*4+1][frow] = __float2bfloat16(vv.y);
                Vs[fd0+j*4+2][frow] = __float2bfloat16(vv.z);
                Vs[fd0+j*4+3][frow] = __float2bfloat16(vv.w);
            }
        }
        __syncthreads();

        float sc[8][4];
        #pragma unroll
        for (int nt = 0; nt < 8; nt++) {
            sc[nt][0]=sc[nt][1]=sc[nt][2]=sc[nt][3]=0.f;
            #pragma unroll
            for (int ks = 0; ks < 4; ks++) {
                uint32_t kb0 = *(const uint32_t*)&Ks[nt*8+g][ks*16+2*tg];
                uint32_t kb1 = *(const uint32_t*)&Ks[nt*8+g][ks*16+2*tg+8];
                mma16816(sc[nt], qa[ks], kb0, kb1);
            }
        }
        if (kt >= 2*qt) {   // diagonal region: elementwise causal mask
            #pragma unroll
            for (int nt = 0; nt < 8; nt++) {
                int col = k0 + nt*8 + 2*tg;
                if (col   > row0)   sc[nt][0] = -1e30f;
                if (col+1 > row0)   sc[nt][1] = -1e30f;
                if (col   > row0+8) sc[nt][2] = -1e30f;
                if (col+1 > row0+8) sc[nt][3] = -1e30f;
            }
        }
        float mx0 = -1e30f, mx1 = -1e30f;
        #pragma unroll
        for (int nt = 0; nt < 8; nt++) {
            mx0 = fmaxf(mx0, fmaxf(sc[nt][0], sc[nt][1]));
            mx1 = fmaxf(mx1, fmaxf(sc[nt][2], sc[nt][3]));
        }
        mx0 = fmaxf(mx0, __shfl_xor_sync(0xffffffffu, mx0, 1));
        mx0 = fmaxf(mx0, __shfl_xor_sync(0xffffffffu, mx0, 2));
        mx1 = fmaxf(mx1, __shfl_xor_sync(0xffffffffu, mx1, 1));
        mx1 = fmaxf(mx1, __shfl_xor_sync(0xffffffffu, mx1, 2));
        float nm0 = fmaxf(m0, mx0), nm1 = fmaxf(m1, mx1);
        float c0 = fexp(m0 - nm0), c1 = fexp(m1 - nm1);
        m0 = nm0; m1 = nm1;

        uint32_t pa[4][4];
        float s0 = 0.f, s1 = 0.f;
        #pragma unroll
        for (int nt = 0; nt < 8; nt++) {
            float e0 = fexp(sc[nt][0]-m0), e1 = fexp(sc[nt][1]-m0);
            float e2 = fexp(sc[nt][2]-m1), e3 = fexp(sc[nt][3]-m1);
            s0 += e0+e1; s1 += e2+e3;
            int ks = nt>>1, hi = (nt&1)*2;
            pa[ks][hi+0] = pack_bf16x2(e0, e1);
            pa[ks][hi+1] = pack_bf16x2(e2, e3);
        }
        s0 += __shfl_xor_sync(0xffffffffu, s0, 1);
        s0 += __shfl_xor_sync(0xffffffffu, s0, 2);
        s1 += __shfl_xor_sync(0xffffffffu, s1, 1);
        s1 += __shfl_xor_sync(0xffffffffu, s1, 2);
        l0 = l0*c0 + s0; l1 = l1*c1 + s1;

        #pragma unroll
        for (int nt = 0; nt < 8; nt++) {
            o[nt][0]*=c0; o[nt][1]*=c0; o[nt][2]*=c1; o[nt][3]*=c1;
            #pragma unroll
            for (int ks = 0; ks < 4; ks++) {
                uint32_t vb0 = *(const uint32_t*)&Vs[nt*8+g][ks*16+2*tg];
                uint32_t vb1 = *(const uint32_t*)&Vs[nt*8+g][ks*16+2*tg+8];
                mma16816(o[nt], pa[ks], vb0, vb1);
            }
        }
    }
    float i0 = 1.f/l0, i1 = 1.f/l1;
    #pragma unroll
    for (int nt = 0; nt < 8; nt++) {
        float2 v0 = make_float2(o[nt][0]*i0, o[nt][1]*i0);
        float2 v1 = make_float2(o[nt][2]*i1, o[nt][3]*i1);
        *(float2*)&O[base + (size_t)row0*Dsz + nt*8 + 2*tg]     = v0;
        *(float2*)&O[base + (size_t)(row0+8)*Dsz + nt*8 + 2*tg] = v1;
    }
}

// ---------------- top-8 (register-local) + softmax + gather + residual ------
__global__ __launch_bounds__(256) void topk_mem_kernel(
    const float* __restrict__ MS, const float* __restrict__ KV,
    float* __restrict__ OUT)
{
    int s = blockIdx.x, bq = blockIdx.y, tid = threadIdx.x;
    int lane = tid & 31, w = tid >> 5;
    __shared__ float rv[8];
    __shared__ int   ri[8];
    __shared__ float topv[8];
    __shared__ int   topi[8];
    __shared__ float tw[8];
    const float* row = MS + ((size_t)bq*Ssz + s)*NKk;

    // per-thread sorted top-8 of its 16 strided elements
    float lv[8]; int li[8];
    #pragma unroll
    for (int k = 0; k < 8; k++) { lv[k] = -1e30f; li[k] = NKk; }
    #pragma unroll
    for (int j = 0; j < 16; j++) {
        int idx = tid + j*256;
        float cv = row[idx]; int ci = idx;
        if (cv > lv[7]) {
            #pragma unroll
            for (int k = 0; k < 8; k++) {
                if (cv > lv[k]) {
                    float tv = lv[k]; int ti = li[k];
                    lv[k] = cv; li[k] = ci;
                    cv = tv; ci = ti;
                }
            }
        }
    }

    // 8 merge rounds: warp shuffle argmax + 8-way final, tie -> lower index
    for (int it = 0; it < 8; it++) {
        float hv = lv[0]; int hi = li[0];
        #pragma unroll
        for (int o = 16; o > 0; o >>= 1) {
            float ov = __shfl_xor_sync(0xffffffffu, hv, o);
            int   oi = __shfl_xor_sync(0xffffffffu, hi, o);
            if (ov > hv || (ov == hv && oi < hi)) { hv = ov; hi = oi; }
        }
        if (lane == 0) { rv[w] = hv; ri[w] = hi; }
        __syncthreads();
        if (tid == 0) {
            float bv = rv[0]; int bi = ri[0];
            #pragma unroll
            for (int k = 1; k < 8; k++)
                if (rv[k] > bv || (rv[k] == bv && ri[k] < bi)) { bv = rv[k]; bi = ri[k]; }
            topv[it] = bv; topi[it] = bi;
        }
        __syncthreads();
        if (li[0] == topi[it]) {          // winner pops its head
            #pragma unroll
            for (int k = 0; k < 7; k++) { lv[k] = lv[k+1]; li[k] = li[k+1]; }
            lv[7] = -1e30f; li[7] = NKk;
        }
        __syncthreads();
    }
    if (tid == 0) {
        float mx = topv[0]; float se = 0.f;
        #pragma unroll
        for (int k = 0; k < 8; k++) { tw[k] = __expf(topv[k]-mx); se += tw[k]; }
        float inv = 1.f/se;
        #pragma unroll
        for (int k = 0; k < 8; k++) tw[k] *= inv;
    }
    __syncthreads();
    float w0 = tw[0], w1 = tw[1], w2 = tw[2], w3 = tw[3];
    float w4 = tw[4], w5 = tw[5], w6 = tw[6], w7 = tw[7];
    size_t i0 = (size_t)topi[0]*Dsz, i1 = (size_t)topi[1]*Dsz;
    size_t i2 = (size_t)topi[2]*Dsz, i3 = (size_t)topi[3]*Dsz;
    size_t i4 = (size_t)topi[4]*Dsz, i5 = (size_t)topi[5]*Dsz;
    size_t i6 = (size_t)topi[6]*Dsz, i7 = (size_t)topi[7]*Dsz;
    float* o = OUT + ((size_t)bq*Ssz + s)*Dsz;
    for (int d = tid; d < Dsz; d += 256) {
        float a = o[d];
        a = fmaf(w0, KV[i0+d], a); a = fmaf(w1, KV[i1+d], a);
        a = fmaf(w2, KV[i2+d], a); a = fmaf(w3, KV[i3+d], a);
        a = fmaf(w4, KV[i4+d], a); a = fmaf(w5, KV[i5+d], a);
        a = fmaf(w6, KV[i6+d], a); a = fmaf(w7, KV[i7+d], a);
        o[d] = a;
    }
}

// ---------------- launch ----------------------------------------------------
extern "C" void kernel_launch(void* const* d_in, const int* in_sizes, int n_in,
                              void* d_out, int out_size)
{
    const float* x    = (const float*)d_in[0];
    const float* imp  = (const float*)d_in[1];
    const float* Wc   = (const float*)d_in[2];
    const float* WQ   = (const float*)d_in[3];
    const float* WK   = (const float*)d_in[4];
    const float* WV   = (const float*)d_in[5];
    const float* Wm   = (const float*)d_in[6];
    const float* cn   = (const float*)d_in[7];
    const float* pool = (const float*)d_in[8];
    const float* kK   = (const float*)d_in[9];
    const float* kV   = (const float*)d_in[10];
    const float* WO   = (const float*)d_in[11];
    const float* g1   = (const float*)d_in[12];
    const float* b1   = (const float*)d_in[13];
    const float* g2   = (const float*)d_in[14];
    const float* b2   = (const float*)d_in[15];
    float* out = (float*)d_out;

    static float* base = nullptr;
    if (!base) cudaGetSymbolAddress((void**)&base, g_scratch);

    float* nx   = base + OFF_NX;
    float* nx2  = base + OFF_NX2;
    float* scp  = base + OFF_SC;
    float* mcp  = base + OFF_MC;
    float* ep   = base + OFF_E;
    float* hp   = base + OFF_H;
    float* qmp  = base + OFF_QM;
    float* qkvp = base + OFF_QKV;
    float* aop  = base + OFF_AO;
    float* msp  = base + OFF_MS;
    float* accP = base + OFF_ACC;
    float* wptr = base + OFF_W;

    const size_t SD = (size_t)Ssz*Dsz;
    const size_t SR = (size_t)Ssz*Rsz;
    const size_t RD = (size_t)Rsz*Dsz;
    const size_t BSD = (size_t)Bsz*Ssz*Dsz;
    const size_t SNK = (size_t)Ssz*NKk;

    zero_kernel<<<(NSLICE*Bsz*5*16 + 255)/256, 256>>>(accP, NSLICE*Bsz*5*16);
    ln_route_kernel<<<dim3(Ssz, Bsz), 256>>>(x, imp, Wc, WQ, WK, WV, g1, b1,
                                             nx, accP, 4, 0);
    finalize_w_kernel<<<1, 256>>>(accP, wptr, 0, 4);
    combine_cT_kernel<<<dim3(Dsz/32, Rsz/32), 256>>>(wptr, cn, scp, 0);
    combine_eT_kernel<<<dim3(Dsz/32, Rsz/32), 256>>>(wptr, pool, ep);
    tgemm_kernel<false><<<dim3(Rsz/128, Ssz/128, Bsz), 256>>>(nx, scp, nullptr, hp,
        Ssz, Rsz, Dsz, 1.f, SD, RD, SR, 0);
    for (int r3 = 0; r3 < 3; r3++)
        tgemm_kernel<false><<<dim3(Dsz/128, Ssz/128, Bsz), 256>>>(hp,
            ep + (size_t)r3*Bsz*RD, nullptr, qkvp + (size_t)r3*BSD,
            Ssz, Dsz, Rsz, 1.f, SR, RD, SD, 0);
    flash_mma_kernel<<<dim3(Ssz/128, Hsz, Bsz), 256>>>(qkvp, qkvp + BSD,
                                                       qkvp + 2*BSD, aop);
    tgemm_kernel<true><<<dim3(Dsz/128, Ssz/128, Bsz), 256>>>(aop, WO, x, out,
        Ssz, Dsz, Dsz, 1.f, SD, 0, SD, SD);
    ln_route_kernel<<<dim3(Ssz, Bsz), 256>>>(out, imp, Wm, Wm, Wm, Wm, g2, b2,
                                             nx2, accP, 1, 4);
    finalize_w_kernel<<<1, 256>>>(accP, wptr, 4, 1);
    combine_cT_kernel<<<dim3(Dsz/32, Rsz/32), 256>>>(wptr, cn, mcp, 4);
    tgemm_kernel<false><<<dim3(Rsz/128, Ssz/128, Bsz), 256>>>(nx2, mcp, nullptr, qmp,
        Ssz, Rsz, Dsz, 1.f, SD, RD, SR, 0);
    tgemm_kernel<false><<<dim3(NKk/128, Ssz/128, Bsz), 256>>>(qmp, kK, nullptr, msp,
        Ssz, NKk, Rsz, 0.0625f, SR, 0, SNK, 0);
    topk_mem_kernel<<<dim3(Ssz, Bsz), 256>>>(msp, kV, out);
}

// round 16
// speedup vs baseline: 1.1756x; 1.0397x over previous
#include <cuda_runtime.h>
#include <cuda_bf16.h>
#include <math.h>
#include <stdint.h>

#define Bsz 2
#define Ssz 2048
#define Dsz 1024
#define Hsz 16
#define DHsz 64
#define Rsz 256
#define NKk 4096
#define NSLICE 32

// ---------------- single scratch arena (one symbol, no allocations) ---------
#define OFF_NX    ((size_t)0)
#define OFF_NX2   (OFF_NX   + (size_t)Bsz*Ssz*Dsz)
#define OFF_SC    (OFF_NX2  + (size_t)Bsz*Ssz*Dsz)
#define OFF_MC    (OFF_SC   + (size_t)Bsz*Dsz*Rsz)
#define OFF_E     (OFF_MC   + (size_t)Bsz*Dsz*Rsz)
#define OFF_H     (OFF_E    + (size_t)3*Bsz*Rsz*Dsz)
#define OFF_QM    (OFF_H    + (size_t)Bsz*Ssz*Rsz)
#define OFF_QKV   (OFF_QM   + (size_t)Bsz*Ssz*Rsz)
#define OFF_AO    (OFF_QKV  + (size_t)3*Bsz*Ssz*Dsz)
#define OFF_MS    (OFF_AO   + (size_t)Bsz*Ssz*Dsz)
#define OFF_ACC   (OFF_MS   + (size_t)Bsz*Ssz*NKk)
#define OFF_W     (OFF_ACC  + (size_t)NSLICE*Bsz*5*16)
#define SCRATCH_TOTAL (OFF_W + (size_t)Bsz*5*16)

__device__ float g_scratch[SCRATCH_TOTAL];

// ---------------- helpers ----------------------------------------------------
__device__ __forceinline__ float fexp(float x) {
    x = fmaxf(x, -80.f);
    float z = x * 1.4426950408889634f;
    float r = rintf(z);
    float f = z - r;
    float p =            0.0013333558f;
    p = fmaf(p, f, 0.0096181291f);
    p = fmaf(p, f, 0.0555041087f);
    p = fmaf(p, f, 0.2402264791f);
    p = fmaf(p, f, 0.6931472028f);
    p = fmaf(p, f, 1.0f);
    int e = (int)r;
    return __int_as_float(__float_as_int(p) + (e << 23));
}

__device__ __forceinline__ uint32_t pack_bf16x2(float lo, float hi) {
    __nv_bfloat162 t = __floats2bfloat162_rn(lo, hi);
    uint32_t u;
    memcpy(&u, &t, 4);
    return u;
}

// ---------------- zero router accumulators ----------------------------------
__global__ void zero_kernel(float* p, int n) {
    int i = blockIdx.x*256 + threadIdx.x;
    if (i < n) p[i] = 0.f;
}

// ------- LayerNorm + router (8 tokens/block, W amortized 8x) ----------------
__global__ __launch_bounds__(256) void ln_route8_kernel(
    const float* __restrict__ X, const float* __restrict__ imp,
    const float* __restrict__ W0, const float* __restrict__ W1,
    const float* __restrict__ W2, const float* __restrict__ W3,
    const float* __restrict__ gamma, const float* __restrict__ beta,
    float* __restrict__ NX, float* __restrict__ accPart,
    int nR, int rbase)
{
    int s0 = blockIdx.x*8, b = blockIdx.y, tid = threadIdx.x;
    int lane = tid & 31, w = tid >> 5;
    __shared__ float xs[8][Dsz];
    __shared__ float lg[8][64];

    // --- LN: warp w handles token s0+w entirely (warp-local reductions) ---
    {
        const float* xr = X + ((size_t)b*Ssz + s0 + w)*Dsz;
        float v[32];
        float lsum = 0.f, lsq = 0.f;
        #pragma unroll
        for (int j = 0; j < 32; j++) {
            float t = xr[lane + j*32];
            v[j] = t; lsum += t; lsq += t*t;
        }
        #pragma unroll
        for (int o = 16; o > 0; o >>= 1) {
            lsum += __shfl_xor_sync(0xffffffffu, lsum, o);
            lsq  += __shfl_xor_sync(0xffffffffu, lsq,  o);
        }
        float mean = lsum / (float)Dsz;
        float var  = lsq / (float)Dsz - mean*mean;
        float rstd = rsqrtf(var + 1e-5f);
        float* nxr = NX + ((size_t)b*Ssz + s0 + w)*Dsz;
        #pragma unroll
        for (int j = 0; j < 32; j++) {
            int i = lane + j*32;
            float nv = (v[j]-mean)*rstd*gamma[i] + beta[i];
            xs[w][i] = nv; nxr[i] = nv;
        }
    }
    __syncthreads();

    // --- router logits: warp handles 8 experts x 8 tokens (64 accs) ---
    if (w < nR*2) {
        int ebase = w*8;
        const float* Wr[8];
        #pragma unroll
        for (int e8 = 0; e8 < 8; e8++) {
            int e = ebase + e8;
            Wr[e8] = (e < 16 ? W0 : (e < 32 ? W1 : (e < 48 ? W2 : W3)))
                     + (size_t)(e & 15)*Dsz;
        }
        float acc[64];
        #pragma unroll
        for (int k = 0; k < 64; k++) acc[k] = 0.f;
        for (int i = lane; i < Dsz; i += 32) {
            float xv[8];
            #pragma unroll
            for (int t = 0; t < 8; t++) xv[t] = xs[t][i];
            #pragma unroll
            for (int e8 = 0; e8 < 8; e8++) {
                float wv = Wr[e8][i];
                #pragma unroll
                for (int t = 0; t < 8; t++)
                    acc[e8*8+t] = fmaf(xv[t], wv, acc[e8*8+t]);
            }
        }
        #pragma unroll
        for (int k = 0; k < 64; k++) {
            float a = acc[k];
            #pragma unroll
            for (int o = 16; o > 0; o >>= 1)
                a += __shfl_xor_sync(0xffffffffu, a, o);
            if (lane == 0) lg[k & 7][ebase + (k >> 3)] = a;
        }
    }
    __syncthreads();

    // --- softmax + importance pool (one thread per (token, router)) ---
    int pairs = 8*nR;
    if (tid < pairs) {
        int t = tid / nR, r = tid - t*nR;
        int s = s0 + t;
        const float* lrow = &lg[t][r*16];
        float mx = -1e30f;
        #pragma unroll
        for (int e = 0; e < 16; e++) mx = fmaxf(mx, lrow[e]);
        float ex[16]; float se = 0.f;
        #pragma unroll
        for (int e = 0; e < 16; e++) { ex[e] = __expf(lrow[e]-mx); se += ex[e]; }
        float wi = imp[(size_t)b*Ssz + s] / se;
        int slice = s & (NSLICE-1);
        float* dst = accPart + ((size_t)(slice*Bsz + b)*5 + rbase + r)*16;
        #pragma unroll
        for (int e = 0; e < 16; e++) atomicAdd(&dst[e], wi*ex[e]);
    }
}

// ---------------- reduce slices + normalize route weights -------------------
__global__ void finalize_w_kernel(const float* __restrict__ accPart,
                                  float* __restrict__ w, int rbase, int nR)
{
    __shared__ float vals[2*5*16];
    int t = threadIdx.x;
    int tot = Bsz*nR*16;
    if (t < tot) {
        int b = t/(nR*16); int r = (t/16) % nR; int e = t & 15;
        float sum = 0.f;
        for (int sl = 0; sl < NSLICE; sl++)
            sum += accPart[((size_t)(sl*Bsz + b)*5 + rbase + r)*16 + e];
        vals[t] = sum;
    }
    __syncthreads();
    if (t < tot) {
        int b = t/(nR*16); int r = (t/16) % nR;
        float den = 1e-8f;
        #pragma unroll
        for (int j = 0; j < 16; j++) den += vals[(b*nR + r)*16 + j];
        w[((b*5) + rbase + r)*16 + (t & 15)] = vals[t] / den;
    }
}

// ------- weighted pool combine TRANSPOSED: [16,D,R] -> scT [B][R][D] --------
__global__ __launch_bounds__(256) void combine_cT_kernel(
    const float* __restrict__ w, const float* __restrict__ pool,
    float* __restrict__ out, int router)
{
    __shared__ float ws[2][16];
    __shared__ float tile[2][32][33];
    int tid = threadIdx.x;
    if (tid < 32) ws[tid>>4][tid&15] = w[((tid>>4)*5 + router)*16 + (tid&15)];
    __syncthreads();
    int tx = tid & 31, ty = tid >> 5;
    int d0 = blockIdx.x*32, r0 = blockIdx.y*32;
    const size_t X = (size_t)Dsz*Rsz;
    #pragma unroll
    for (int dr = 0; dr < 4; dr++) {
        int dd = ty + dr*8;
        float a0 = 0.f, a1 = 0.f;
        #pragma unroll
        for (int n = 0; n < 16; n++) {
            float p = pool[(size_t)n*X + (size_t)(d0+dd)*Rsz + r0 + tx];
            a0 += ws[0][n]*p; a1 += ws[1][n]*p;
        }
        tile[0][dd][tx] = a0; tile[1][dd][tx] = a1;
    }
    __syncthreads();
    #pragma unroll
    for (int dr = 0; dr < 4; dr++) {
        int rr = ty + dr*8;
        out[(size_t)(r0+rr)*Dsz + d0 + tx]     = tile[0][tx][rr];
        out[X + (size_t)(r0+rr)*Dsz + d0 + tx] = tile[1][tx][rr];
    }
}

// ------- expand combine TRANSPOSED: [16,R,D] -> eT [3*B][D][R] --------------
__global__ __launch_bounds__(256) void combine_eT_kernel(
    const float* __restrict__ w, const float* __restrict__ pool,
    float* __restrict__ out)
{
    __shared__ float ws[6][16];
    __shared__ float tile[6][32][33];
    int tid = threadIdx.x;
    if (tid < 96) {
        int slot = tid>>4, e = tid&15;
        int r3 = slot>>1, b = slot&1;
        ws[slot][e] = w[(b*5 + 1 + r3)*16 + e];
    }
    __syncthreads();
    int tx = tid&31, ty = tid>>5;
    int d0 = blockIdx.x*32, r0 = blockIdx.y*32;
    const size_t X = (size_t)Rsz*Dsz;
    #pragma unroll
    for (int dr = 0; dr < 4; dr++) {
        int rr = ty + dr*8;
        float a[6] = {0.f,0.f,0.f,0.f,0.f,0.f};
        #pragma unroll
        for (int n = 0; n < 16; n++) {
            float p = pool[(size_t)n*X + (size_t)(r0+rr)*Dsz + d0+tx];
            #pragma unroll
            for (int sl = 0; sl < 6; sl++) a[sl] += ws[sl][n]*p;
        }
        #pragma unroll
        for (int sl = 0; sl < 6; sl++) tile[sl][rr][tx] = a[sl];
    }
    __syncthreads();
    #pragma unroll
    for (int dr = 0; dr < 4; dr++) {
        int dd = ty + dr*8;
        #pragma unroll
        for (int sl = 0; sl < 6; sl++)
            out[(size_t)sl*X + (size_t)(d0+dd)*Rsz + r0+tx] = tile[sl][tx][dd];
    }
}

// ---------------- tf32 tensor-core GEMM (NT): C = alpha*A[M,K] x B[N,K]^T ---
// (round-7 proven version: LDG + cvt.rna staging, 32-k chunks, 32KB smem)
template<bool RESID>
__global__ __launch_bounds__(256) void tgemm_kernel(
    const float* __restrict__ A, const float* __restrict__ Bm,
    const float* __restrict__ Rsrc, float* __restrict__ C,
    int M, int N, int K, float alpha,
    size_t sA, size_t sB, size_t sC, size_t sR)
{
    __shared__ uint32_t As[4*8*4*32];
    __shared__ uint32_t Bs[4*16*2*32];
    A += (size_t)blockIdx.z*sA; Bm += (size_t)blockIdx.z*sB;
    C += (size_t)blockIdx.z*sC; if (RESID) Rsrc += (size_t)blockIdx.z*sR;
    int tid = threadIdx.x, lane = tid&31, warp = tid>>5;
    int wm = warp>>2, wn = warp&3;
    int bm = blockIdx.y<<7, bn = blockIdx.x<<7;

    float c[4][4][4];
    #pragma unroll
    for (int i=0;i<4;i++)
        #pragma unroll
        for(int j=0;j<4;j++)
            #pragma unroll
            for(int f=0;f<4;f++) c[i][j][f]=0.f;

    int row = tid>>1;
    int qb  = (tid&1)*4;
    const float* Aro = A + (size_t)(bm+row)*K;
    const float* Bro = Bm + (size_t)(bn+row)*K;
    int amt = row>>4, arm = row&15;
    int bnt = row>>3, brn = row&7;
    uint32_t* Abase = As + ((amt*4 + (arm>>3))*32) + (arm&7)*4;
    uint32_t* Bbase = Bs + (bnt*2)*32 + brn*4;

    for (int k0 = 0; k0 < K; k0 += 32) {
        #pragma unroll
        for (int i = 0; i < 4; i++) {
            int q = qb + i;
            float4 v = *(const float4*)(Aro + k0 + q*4);
            uint4 u;
            asm("cvt.rna.tf32.f32 %0,%1;":"=r"(u.x):"f"(v.x));
            asm("cvt.rna.tf32.f32 %0,%1;":"=r"(u.y):"f"(v.y));
            asm("cvt.rna.tf32.f32 %0,%1;":"=r"(u.z):"f"(v.z));
            asm("cvt.rna.tf32.f32 %0,%1;":"=r"(u.w):"f"(v.w));
            *(uint4*)(Abase + (q>>1)*1024 + (q&1)*64) = u;
        }
        #pragma unroll
        for (int i = 0; i < 4; i++) {
            int q = qb + i;
            float4 v = *(const float4*)(Bro + k0 + q*4);
            uint4 u;
            asm("cvt.rna.tf32.f32 %0,%1;":"=r"(u.x):"f"(v.x));
            asm("cvt.rna.tf32.f32 %0,%1;":"=r"(u.y):"f"(v.y));
            asm("cvt.rna.tf32.f32 %0,%1;":"=r"(u.z):"f"(v.z));
            asm("cvt.rna.tf32.f32 %0,%1;":"=r"(u.w):"f"(v.w));
            *(uint4*)(Bbase + (q>>1)*1024 + (q&1)*32) = u;
        }
        __syncthreads();
        #pragma unroll
        for (int k8 = 0; k8 < 4; k8++) {
            uint32_t a[4][4], b[4][2];
            #pragma unroll
            for (int mt = 0; mt < 4; mt++) {
                const uint32_t* p = As + k8*1024 + ((wm*4+mt)*4)*32 + lane;
                a[mt][0]=p[0]; a[mt][1]=p[32]; a[mt][2]=p[64]; a[mt][3]=p[96];
            }
            #pragma unroll
            for (int nt = 0; nt < 4; nt++) {
                const uint32_t* p = Bs + k8*1024 + ((wn*4+nt)*2)*32 + lane;
                b[nt][0]=p[0]; b[nt][1]=p[32];
            }
            #pragma unroll
            for (int mt = 0; mt < 4; mt++)
                #pragma unroll
                for (int nt = 0; nt < 4; nt++)
                    asm volatile(
                        "mma.sync.aligned.m16n8k8.row.col.f32.tf32.tf32.f32 "
                        "{%0,%1,%2,%3}, {%4,%5,%6,%7}, {%8,%9}, {%0,%1,%2,%3};"
                        : "+f"(c[mt][nt][0]), "+f"(c[mt][nt][1]),
                          "+f"(c[mt][nt][2]), "+f"(c[mt][nt][3])
                        : "r"(a[mt][0]), "r"(a[mt][1]), "r"(a[mt][2]), "r"(a[mt][3]),
                          "r"(b[nt][0]), "r"(b[nt][1]));
        }
        __syncthreads();
    }
    int g = lane>>2, tg = lane&3;
    #pragma unroll
    for (int mt = 0; mt < 4; mt++) {
        size_t r0 = (size_t)(bm + wm*64 + mt*16 + g);
        size_t r1 = r0 + 8;
        #pragma unroll
        for (int nt = 0; nt < 4; nt++) {
            int col = bn + wn*32 + nt*8 + tg*2;
            float2 v0 = make_float2(alpha*c[mt][nt][0], alpha*c[mt][nt][1]);
            float2 v1 = make_float2(alpha*c[mt][nt][2], alpha*c[mt][nt][3]);
            if (RESID) {
                float2 q0 = *(const float2*)&Rsrc[r0*N + col];
                float2 q1 = *(const float2*)&Rsrc[r1*N + col];
                v0.x += q0.x; v0.y += q0.y; v1.x += q1.x; v1.y += q1.y;
            }
            *(float2*)&C[r0*N + col] = v0;
            *(float2*)&C[r1*N + col] = v1;
        }
    }
}

// ---------------- bf16 tensor-core causal flash attention (dh=64) -----------
// 256 threads = 8 warps; CTA handles 128 q-rows; 64-key tiles shared by all.
__device__ __forceinline__ void mma16816(float* c, const uint32_t* a,
                                         uint32_t b0, uint32_t b1) {
    asm volatile("mma.sync.aligned.m16n8k16.row.col.f32.bf16.bf16.f32 "
        "{%0,%1,%2,%3}, {%4,%5,%6,%7}, {%8,%9}, {%0,%1,%2,%3};"
        : "+f"(c[0]),"+f"(c[1]),"+f"(c[2]),"+f"(c[3])
        : "r"(a[0]),"r"(a[1]),"r"(a[2]),"r"(a[3]), "r"(b0),"r"(b1));
}

__global__ __launch_bounds__(256) void flash_mma_kernel(
    const float* __restrict__ Q, const float* __restrict__ Kt,
    const float* __restrict__ V, float* __restrict__ O)
{
    __shared__ __nv_bfloat16 Ks[64][72];   // K tile [key][d]  (also Q staging)
    __shared__ __nv_bfloat16 Vs[64][72];   // V tile transposed [d][key]
    int qt = blockIdx.x, h = blockIdx.y, b = blockIdx.z;
    int tid = threadIdx.x, lane = tid&31, w = tid>>5;
    int g = lane>>2, tg = lane&3;
    const size_t base = ((size_t)b*Ssz)*Dsz + h*DHsz;
    int qb = qt*128;
    int frow = tid>>2, fd0 = (tid&3)*16;   // fill: 16 floats (4x float4) per thread
    int lrow = (w&3)*16 + g;               // staging row for this warp's fragments
    int row0 = qb + w*16 + g;              // this thread's global q rows: row0, row0+8

    uint32_t qa[4][4];
    // stage Q rows qb..qb+63 (scaled 1/8), warps 0-3 extract
    {
        const float* src = Q + base + (size_t)(qb+frow)*Dsz + fd0;
        #pragma unroll
        for (int j = 0; j < 4; j++) {
            float4 v = *(const float4*)(src + j*4);
            *(__nv_bfloat162*)&Ks[frow][fd0+j*4]   = __floats2bfloat162_rn(v.x*0.125f, v.y*0.125f);
            *(__nv_bfloat162*)&Ks[frow][fd0+j*4+2] = __floats2bfloat162_rn(v.z*0.125f, v.w*0.125f);
        }
    }
    __syncthreads();
    if (w < 4) {
        #pragma unroll
        for (int ks = 0; ks < 4; ks++) {
            qa[ks][0] = *(const uint32_t*)&Ks[lrow  ][ks*16+2*tg];
            qa[ks][1] = *(const uint32_t*)&Ks[lrow+8][ks*16+2*tg];
            qa[ks][2] = *(const uint32_t*)&Ks[lrow  ][ks*16+2*tg+8];
            qa[ks][3] = *(const uint32_t*)&Ks[lrow+8][ks*16+2*tg+8];
        }
    }
    __syncthreads();
    // stage Q rows qb+64..qb+127, warps 4-7 extract
    {
        const float* src = Q + base + (size_t)(qb+64+frow)*Dsz + fd0;
        #pragma unroll
        for (int j = 0; j < 4; j++) {
            float4 v = *(const float4*)(src + j*4);
            *(__nv_bfloat162*)&Ks[frow][fd0+j*4]   = __floats2bfloat162_rn(v.x*0.125f, v.y*0.125f);
            *(__nv_bfloat162*)&Ks[frow][fd0+j*4+2] = __floats2bfloat162_rn(v.z*0.125f, v.w*0.125f);
        }
    }
    __syncthreads();
    if (w >= 4) {
        #pragma unroll
        for (int ks = 0; ks < 4; ks++) {
            qa[ks][0] = *(const uint32_t*)&Ks[lrow  ][ks*16+2*tg];
            qa[ks][1] = *(const uint32_t*)&Ks[lrow+8][ks*16+2*tg];
            qa[ks][2] = *(const uint32_t*)&Ks[lrow  ][ks*16+2*tg+8];
            qa[ks][3] = *(const uint32_t*)&Ks[lrow+8][ks*16+2*tg+8];
        }
    }

    float o[8][4];
    #pragma unroll
    for (int nt = 0; nt < 8; nt++)
        o[nt][0]=o[nt][1]=o[nt][2]=o[nt][3]=0.f;
    float m0=-1e30f, m1=-1e30f, l0=0.f, l1=0.f;

    int ntiles = 2*qt + 2;
    for (int kt = 0; kt < ntiles; kt++) {
        int k0 = kt*64;
        __syncthreads();
        {   // fill K tile [key][d] and V tile transposed [d][key]
            const float* ksrc = Kt + base + (size_t)(k0+frow)*Dsz + fd0;
            const float* vsrc = V  + base + (size_t)(k0+frow)*Dsz + fd0;
            #pragma unroll
            for (int j = 0; j < 4; j++) {
                float4 kv = *(const float4*)(ksrc + j*4);
                *(__nv_bfloat162*)&Ks[frow][fd0+j*4]   = __floats2bfloat162_rn(kv.x, kv.y);
                *(__nv_bfloat162*)&Ks[frow][fd0+j*4+2] = __floats2bfloat162_rn(kv.z, kv.w);
                float4 vv = *(const float4*)(vsrc + j*4);
                Vs[fd0+j*4  ][frow] = __float2bfloat16(vv.x);
                Vs[fd0+j*4+1][frow] = __float2bfloat16(vv.y);
                Vs[fd0+j*4+2][frow] = __float2bfloat16(vv.z);
                Vs[fd0+j*4+3][frow] = __float2bfloat16(vv.w);
            }
        }
        __syncthreads();

        float sc[8][4];
        #pragma unroll
        for (int nt = 0; nt < 8; nt++) {
            sc[nt][0]=sc[nt][1]=sc[nt][2]=sc[nt][3]=0.f;
            #pragma unroll
            for (int ks = 0; ks < 4; ks++) {
                uint32_t kb0 = *(const uint32_t*)&Ks[nt*8+g][ks*16+2*tg];
                uint32_t kb1 = *(const uint32_t*)&Ks[nt*8+g][ks*16+2*tg+8];
                mma16816(sc[nt], qa[ks], kb0, kb1);
            }
        }
        if (kt >= 2*qt) {   // diagonal region: elementwise causal mask
            #pragma unroll
            for (int nt = 0; nt < 8; nt++) {
                int col = k0 + nt*8 + 2*tg;
                if (col   > row0)   sc[nt][0] = -1e30f;
                if (col+1 > row0)   sc[nt][1] = -1e30f;
                if (col   > row0+8) sc[nt][2] = -1e30f;
                if (col+1 > row0+8) sc[nt][3] = -1e30f;
            }
        }
        float mx0 = -1e30f, mx1 = -1e30f;
        #pragma unroll
        for (int nt = 0; nt < 8; nt++) {
            mx0 = fmaxf(mx0, fmaxf(sc[nt][0], sc[nt][1]));
            mx1 = fmaxf(mx1, fmaxf(sc[nt][2], sc[nt][3]));
        }
        mx0 = fmaxf(mx0, __shfl_xor_sync(0xffffffffu, mx0, 1));
        mx0 = fmaxf(mx0, __shfl_xor_sync(0xffffffffu, mx0, 2));
        mx1 = fmaxf(mx1, __shfl_xor_sync(0xffffffffu, mx1, 1));
        mx1 = fmaxf(mx1, __shfl_xor_sync(0xffffffffu, mx1, 2));
        float nm0 = fmaxf(m0, mx0), nm1 = fmaxf(m1, mx1);
        float c0 = fexp(m0 - nm0), c1 = fexp(m1 - nm1);
        m0 = nm0; m1 = nm1;

        uint32_t pa[4][4];
        float s0 = 0.f, s1 = 0.f;
        #pragma unroll
        for (int nt = 0; nt < 8; nt++) {
            float e0 = fexp(sc[nt][0]-m0), e1 = fexp(sc[nt][1]-m0);
            float e2 = fexp(sc[nt][2]-m1), e3 = fexp(sc[nt][3]-m1);
            s0 += e0+e1; s1 += e2+e3;
            int ks = nt>>1, hi = (nt&1)*2;
            pa[ks][hi+0] = pack_bf16x2(e0, e1);
            pa[ks][hi+1] = pack_bf16x2(e2, e3);
        }
        s0 += __shfl_xor_sync(0xffffffffu, s0, 1);
        s0 += __shfl_xor_sync(0xffffffffu, s0, 2);
        s1 += __shfl_xor_sync(0xffffffffu, s1, 1);
        s1 += __shfl_xor_sync(0xffffffffu, s1, 2);
        l0 = l0*c0 + s0; l1 = l1*c1 + s1;

        #pragma unroll
        for (int nt = 0; nt < 8; nt++) {
            o[nt][0]*=c0; o[nt][1]*=c0; o[nt][2]*=c1; o[nt][3]*=c1;
            #pragma unroll
            for (int ks = 0; ks < 4; ks++) {
                uint32_t vb0 = *(const uint32_t*)&Vs[nt*8+g][ks*16+2*tg];
                uint32_t vb1 = *(const uint32_t*)&Vs[nt*8+g][ks*16+2*tg+8];
                mma16816(o[nt], pa[ks], vb0, vb1);
            }
        }
    }
    float i0 = 1.f/l0, i1 = 1.f/l1;
    #pragma unroll
    for (int nt = 0; nt < 8; nt++) {
        float2 v0 = make_float2(o[nt][0]*i0, o[nt][1]*i0);
        float2 v1 = make_float2(o[nt][2]*i1, o[nt][3]*i1);
        *(float2*)&O[base + (size_t)row0*Dsz + nt*8 + 2*tg]     = v0;
        *(float2*)&O[base + (size_t)(row0+8)*Dsz + nt*8 + 2*tg] = v1;
    }
}

// ---------------- top-8 (register-local) + softmax + gather + residual ------
__global__ __launch_bounds__(256) void topk_mem_kernel(
    const float* __restrict__ MS, const float* __restrict__ KV,
    float* __restrict__ OUT)
{
    int s = blockIdx.x, bq = blockIdx.y, tid = threadIdx.x;
    int lane = tid & 31, w = tid >> 5;
    __shared__ float rv[8];
    __shared__ int   ri[8];
    __shared__ float topv[8];
    __shared__ int   topi[8];
    __shared__ float tw[8];
    const float* row = MS + ((size_t)bq*Ssz + s)*NKk;

    float lv[8]; int li[8];
    #pragma unroll
    for (int k = 0; k < 8; k++) { lv[k] = -1e30f; li[k] = NKk; }
    #pragma unroll
    for (int j = 0; j < 16; j++) {
        int idx = tid + j*256;
        float cv = row[idx]; int ci = idx;
        if (cv > lv[7]) {
            #pragma unroll
            for (int k = 0; k < 8; k++) {
                if (cv > lv[k]) {
                    float tv = lv[k]; int ti = li[k];
                    lv[k] = cv; li[k] = ci;
                    cv = tv; ci = ti;
                }
            }
        }
    }

    for (int it = 0; it < 8; it++) {
        float hv = lv[0]; int hi = li[0];
        #pragma unroll
        for (int o = 16; o > 0; o >>= 1) {
            float ov = __shfl_xor_sync(0xffffffffu, hv, o);
            int   oi = __shfl_xor_sync(0xffffffffu, hi, o);
            if (ov > hv || (ov == hv && oi < hi)) { hv = ov; hi = oi; }
        }
        if (lane == 0) { rv[w] = hv; ri[w] = hi; }
        __syncthreads();
        if (tid == 0) {
            float bv = rv[0]; int bi = ri[0];
            #pragma unroll
            for (int k = 1; k < 8; k++)
                if (rv[k] > bv || (rv[k] == bv && ri[k] < bi)) { bv = rv[k]; bi = ri[k]; }
            topv[it] = bv; topi[it] = bi;
        }
        __syncthreads();
        if (li[0] == topi[it]) {
            #pragma unroll
            for (int k = 0; k < 7; k++) { lv[k] = lv[k+1]; li[k] = li[k+1]; }
            lv[7] = -1e30f; li[7] = NKk;
        }
        __syncthreads();
    }
    if (tid == 0) {
        float mx = topv[0]; float se = 0.f;
        #pragma unroll
        for (int k = 0; k < 8; k++) { tw[k] = __expf(topv[k]-mx); se += tw[k]; }
        float inv = 1.f/se;
        #pragma unroll
        for (int k = 0; k < 8; k++) tw[k] *= inv;
    }
    __syncthreads();
    float w0 = tw[0], w1 = tw[1], w2 = tw[2], w3 = tw[3];
    float w4 = tw[4], w5 = tw[5], w6 = tw[6], w7 = tw[7];
    size_t i0 = (size_t)topi[0]*Dsz, i1 = (size_t)topi[1]*Dsz;
    size_t i2 = (size_t)topi[2]*Dsz, i3 = (size_t)topi[3]*Dsz;
    size_t i4 = (size_t)topi[4]*Dsz, i5 = (size_t)topi[5]*Dsz;
    size_t i6 = (size_t)topi[6]*Dsz, i7 = (size_t)topi[7]*Dsz;
    float* o = OUT + ((size_t)bq*Ssz + s)*Dsz;
    for (int d = tid; d < Dsz; d += 256) {
        float a = o[d];
        a = fmaf(w0, KV[i0+d], a); a = fmaf(w1, KV[i1+d], a);
        a = fmaf(w2, KV[i2+d], a); a = fmaf(w3, KV[i3+d], a);
        a = fmaf(w4, KV[i4+d], a); a = fmaf(w5, KV[i5+d], a);
        a = fmaf(w6, KV[i6+d], a); a = fmaf(w7, KV[i7+d], a);
        o[d] = a;
    }
}

// ---------------- launch ----------------------------------------------------
extern "C" void kernel_launch(void* const* d_in, const int* in_sizes, int n_in,
                              void* d_out, int out_size)
{
    const float* x    = (const float*)d_in[0];
    const float* imp  = (const float*)d_in[1];
    const float* Wc   = (const float*)d_in[2];
    const float* WQ   = (const float*)d_in[3];
    const float* WK   = (const float*)d_in[4];
    const float* WV   = (const float*)d_in[5];
    const float* Wm   = (const float*)d_in[6];
    const float* cn   = (const float*)d_in[7];
    const float* pool = (const float*)d_in[8];
    const float* kK   = (const float*)d_in[9];
    const float* kV   = (const float*)d_in[10];
    const float* WO   = (const float*)d_in[11];
    const float* g1   = (const float*)d_in[12];
    const float* b1   = (const float*)d_in[13];
    const float* g2   = (const float*)d_in[14];
    const float* b2   = (const float*)d_in[15];
    float* out = (float*)d_out;

    static float* base = nullptr;
    if (!base) cudaGetSymbolAddress((void**)&base, g_scratch);

    float* nx   = base + OFF_NX;
    float* nx2  = base + OFF_NX2;
    float* scp  = base + OFF_SC;
    float* mcp  = base + OFF_MC;
    float* ep   = base + OFF_E;
    float* hp   = base + OFF_H;
    float* qmp  = base + OFF_QM;
    float* qkvp = base + OFF_QKV;
    float* aop  = base + OFF_AO;
    float* msp  = base + OFF_MS;
    float* accP = base + OFF_ACC;
    float* wptr = base + OFF_W;

    const size_t SD = (size_t)Ssz*Dsz;
    const size_t SR = (size_t)Ssz*Rsz;
    const size_t RD = (size_t)Rsz*Dsz;
    const size_t BSD = (size_t)Bsz*Ssz*Dsz;
    const size_t SNK = (size_t)Ssz*NKk;

    zero_kernel<<<(NSLICE*Bsz*5*16 + 255)/256, 256>>>(accP, NSLICE*Bsz*5*16);
    ln_route8_kernel<<<dim3(Ssz/8, Bsz), 256>>>(x, imp, Wc, WQ, WK, WV, g1, b1,
                                                nx, accP, 4, 0);
    finalize_w_kernel<<<1, 256>>>(accP, wptr, 0, 4);
    combine_cT_kernel<<<dim3(Dsz/32, Rsz/32), 256>>>(wptr, cn, scp, 0);
    combine_eT_kernel<<<dim3(Dsz/32, Rsz/32), 256>>>(wptr, pool, ep);
    tgemm_kernel<false><<<dim3(Rsz/128, Ssz/128, Bsz), 256>>>(nx, scp, nullptr, hp,
        Ssz, Rsz, Dsz, 1.f, SD, RD, SR, 0);
    for (int r3 = 0; r3 < 3; r3++)
        tgemm_kernel<false><<<dim3(Dsz/128, Ssz/128, Bsz), 256>>>(hp,
            ep + (size_t)r3*Bsz*RD, nullptr, qkvp + (size_t)r3*BSD,
            Ssz, Dsz, Rsz, 1.f, SR, RD, SD, 0);
    flash_mma_kernel<<<dim3(Ssz/128, Hsz, Bsz), 256>>>(qkvp, qkvp + BSD,
                                                       qkvp + 2*BSD, aop);
    tgemm_kernel<true><<<dim3(Dsz/128, Ssz/128, Bsz), 256>>>(aop, WO, x, out,
        Ssz, Dsz, Dsz, 1.f, SD, 0, SD, SD);
    ln_route8_kernel<<<dim3(Ssz/8, Bsz), 256>>>(out, imp, Wm, Wm, Wm, Wm, g2, b2,
                                                nx2, accP, 1, 4);
    finalize_w_kernel<<<1, 256>>>(accP, wptr, 4, 1);
    combine_cT_kernel<<<dim3(Dsz/32, Rsz/32), 256>>>(wptr, cn, mcp, 4);
    tgemm_kernel<false><<<dim3(Rsz/128, Ssz/128, Bsz), 256>>>(nx2, mcp, nullptr, qmp,
        Ssz, Rsz, Dsz, 1.f, SD, RD, SR, 0);
    tgemm_kernel<false><<<dim3(NKk/128, Ssz/128, Bsz), 256>>>(qmp, kK, nullptr, msp,
        Ssz, NKk, Rsz, 0.0625f, SR, 0, SNK, 0);
    topk_mem_kernel<<<dim3(Ssz, Bsz), 256>>>(msp, kV, out);
}

// round 17
// speedup vs baseline: 1.2758x; 1.0852x over previous
#include <cuda_runtime.h>
#include <cuda_bf16.h>
#include <math.h>
#include <stdint.h>

#define Bsz 2
#define Ssz 2048
#define Dsz 1024
#define Hsz 16
#define DHsz 64
#define Rsz 256
#define NKk 4096
#define NSLICE 32

// ---------------- single scratch arena (one symbol, no allocations) ---------
#define OFF_NX    ((size_t)0)
#define OFF_NX2   (OFF_NX   + (size_t)Bsz*Ssz*Dsz)
#define OFF_SC    (OFF_NX2  + (size_t)Bsz*Ssz*Dsz)
#define OFF_MC    (OFF_SC   + (size_t)Bsz*Dsz*Rsz)
#define OFF_E     (OFF_MC   + (size_t)Bsz*Dsz*Rsz)
#define OFF_H     (OFF_E    + (size_t)3*Bsz*Rsz*Dsz)
#define OFF_QM    (OFF_H    + (size_t)Bsz*Ssz*Rsz)
#define OFF_QKV   (OFF_QM   + (size_t)Bsz*Ssz*Rsz)
#define OFF_AO    (OFF_QKV  + (size_t)3*Bsz*Ssz*Dsz)
#define OFF_MS    (OFF_AO   + (size_t)Bsz*Ssz*Dsz)
#define OFF_ACC   (OFF_MS   + (size_t)Bsz*Ssz*NKk)
#define OFF_W     (OFF_ACC  + (size_t)NSLICE*Bsz*5*16)
#define SCRATCH_TOTAL (OFF_W + (size_t)Bsz*5*16)

__device__ float g_scratch[SCRATCH_TOTAL];

// ---------------- helpers ----------------------------------------------------
__device__ __forceinline__ float fexp(float x) {
    x = fmaxf(x, -80.f);
    float z = x * 1.4426950408889634f;
    float r = rintf(z);
    float f = z - r;
    float p =            0.0013333558f;
    p = fmaf(p, f, 0.0096181291f);
    p = fmaf(p, f, 0.0555041087f);
    p = fmaf(p, f, 0.2402264791f);
    p = fmaf(p, f, 0.6931472028f);
    p = fmaf(p, f, 1.0f);
    int e = (int)r;
    return __int_as_float(__float_as_int(p) + (e << 23));
}

__device__ __forceinline__ uint32_t pack_bf16x2(float lo, float hi) {
    __nv_bfloat162 t = __floats2bfloat162_rn(lo, hi);
    uint32_t u;
    memcpy(&u, &t, 4);
    return u;
}

// ---------------- zero kernel ------------------------------------------------
__global__ void zero_kernel(float* p, int n) {
    int i = blockIdx.x*256 + threadIdx.x;
    if (i < n) p[i] = 0.f;
}

// ------- LayerNorm + router (8 tokens/block, W amortized 8x) ----------------
__global__ __launch_bounds__(256) void ln_route8_kernel(
    const float* __restrict__ X, const float* __restrict__ imp,
    const float* __restrict__ W0, const float* __restrict__ W1,
    const float* __restrict__ W2, const float* __restrict__ W3,
    const float* __restrict__ gamma, const float* __restrict__ beta,
    float* __restrict__ NX, float* __restrict__ accPart,
    int nR, int rbase)
{
    int s0 = blockIdx.x*8, b = blockIdx.y, tid = threadIdx.x;
    int lane = tid & 31, w = tid >> 5;
    __shared__ float xs[8][Dsz];
    __shared__ float lg[8][64];

    {
        const float* xr = X + ((size_t)b*Ssz + s0 + w)*Dsz;
        float v[32];
        float lsum = 0.f, lsq = 0.f;
        #pragma unroll
        for (int j = 0; j < 32; j++) {
            float t = xr[lane + j*32];
            v[j] = t; lsum += t; lsq += t*t;
        }
        #pragma unroll
        for (int o = 16; o > 0; o >>= 1) {
            lsum += __shfl_xor_sync(0xffffffffu, lsum, o);
            lsq  += __shfl_xor_sync(0xffffffffu, lsq,  o);
        }
        float mean = lsum / (float)Dsz;
        float var  = lsq / (float)Dsz - mean*mean;
        float rstd = rsqrtf(var + 1e-5f);
        float* nxr = NX + ((size_t)b*Ssz + s0 + w)*Dsz;
        #pragma unroll
        for (int j = 0; j < 32; j++) {
            int i = lane + j*32;
            float nv = (v[j]-mean)*rstd*gamma[i] + beta[i];
            xs[w][i] = nv; nxr[i] = nv;
        }
    }
    __syncthreads();

    if (w < nR*2) {
        int ebase = w*8;
        const float* Wr[8];
        #pragma unroll
        for (int e8 = 0; e8 < 8; e8++) {
            int e = ebase + e8;
            Wr[e8] = (e < 16 ? W0 : (e < 32 ? W1 : (e < 48 ? W2 : W3)))
                     + (size_t)(e & 15)*Dsz;
        }
        float acc[64];
        #pragma unroll
        for (int k = 0; k < 64; k++) acc[k] = 0.f;
        for (int i = lane; i < Dsz; i += 32) {
            float xv[8];
            #pragma unroll
            for (int t = 0; t < 8; t++) xv[t] = xs[t][i];
            #pragma unroll
            for (int e8 = 0; e8 < 8; e8++) {
                float wv = Wr[e8][i];
                #pragma unroll
                for (int t = 0; t < 8; t++)
                    acc[e8*8+t] = fmaf(xv[t], wv, acc[e8*8+t]);
            }
        }
        #pragma unroll
        for (int k = 0; k < 64; k++) {
            float a = acc[k];
            #pragma unroll
            for (int o = 16; o > 0; o >>= 1)
                a += __shfl_xor_sync(0xffffffffu, a, o);
            if (lane == 0) lg[k & 7][ebase + (k >> 3)] = a;
        }
    }
    __syncthreads();

    int pairs = 8*nR;
    if (tid < pairs) {
        int t = tid / nR, r = tid - t*nR;
        int s = s0 + t;
        const float* lrow = &lg[t][r*16];
        float mx = -1e30f;
        #pragma unroll
        for (int e = 0; e < 16; e++) mx = fmaxf(mx, lrow[e]);
        float ex[16]; float se = 0.f;
        #pragma unroll
        for (int e = 0; e < 16; e++) { ex[e] = __expf(lrow[e]-mx); se += ex[e]; }
        float wi = imp[(size_t)b*Ssz + s] / se;
        int slice = s & (NSLICE-1);
        float* dst = accPart + ((size_t)(slice*Bsz + b)*5 + rbase + r)*16;
        #pragma unroll
        for (int e = 0; e < 16; e++) atomicAdd(&dst[e], wi*ex[e]);
    }
}

// ---------------- reduce slices + normalize route weights -------------------
__global__ void finalize_w_kernel(const float* __restrict__ accPart,
                                  float* __restrict__ w, int rbase, int nR)
{
    __shared__ float vals[2*5*16];
    int t = threadIdx.x;
    int tot = Bsz*nR*16;
    if (t < tot) {
        int b = t/(nR*16); int r = (t/16) % nR; int e = t & 15;
        float sum = 0.f;
        for (int sl = 0; sl < NSLICE; sl++)
            sum += accPart[((size_t)(sl*Bsz + b)*5 + rbase + r)*16 + e];
        vals[t] = sum;
    }
    __syncthreads();
    if (t < tot) {
        int b = t/(nR*16); int r = (t/16) % nR;
        float den = 1e-8f;
        #pragma unroll
        for (int j = 0; j < 16; j++) den += vals[(b*nR + r)*16 + j];
        w[((b*5) + rbase + r)*16 + (t & 15)] = vals[t] / den;
    }
}

// ------- weighted pool combine TRANSPOSED: [16,D,R] -> scT [B][R][D] --------
__global__ __launch_bounds__(256) void combine_cT_kernel(
    const float* __restrict__ w, const float* __restrict__ pool,
    float* __restrict__ out, int router)
{
    __shared__ float ws[2][16];
    __shared__ float tile[2][32][33];
    int tid = threadIdx.x;
    if (tid < 32) ws[tid>>4][tid&15] = w[((tid>>4)*5 + router)*16 + (tid&15)];
    __syncthreads();
    int tx = tid & 31, ty = tid >> 5;
    int d0 = blockIdx.x*32, r0 = blockIdx.y*32;
    const size_t X = (size_t)Dsz*Rsz;
    #pragma unroll
    for (int dr = 0; dr < 4; dr++) {
        int dd = ty + dr*8;
        float a0 = 0.f, a1 = 0.f;
        #pragma unroll
        for (int n = 0; n < 16; n++) {
            float p = pool[(size_t)n*X + (size_t)(d0+dd)*Rsz + r0 + tx];
            a0 += ws[0][n]*p; a1 += ws[1][n]*p;
        }
        tile[0][dd][tx] = a0; tile[1][dd][tx] = a1;
    }
    __syncthreads();
    #pragma unroll
    for (int dr = 0; dr < 4; dr++) {
        int rr = ty + dr*8;
        out[(size_t)(r0+rr)*Dsz + d0 + tx]     = tile[0][tx][rr];
        out[X + (size_t)(r0+rr)*Dsz + d0 + tx] = tile[1][tx][rr];
    }
}

// ------- expand combine TRANSPOSED: [16,R,D] -> eT [3*B][D][R] --------------
__global__ __launch_bounds__(256) void combine_eT_kernel(
    const float* __restrict__ w, const float* __restrict__ pool,
    float* __restrict__ out)
{
    __shared__ float ws[6][16];
    __shared__ float tile[6][32][33];
    int tid = threadIdx.x;
    if (tid < 96) {
        int slot = tid>>4, e = tid&15;
        int r3 = slot>>1, b = slot&1;
        ws[slot][e] = w[(b*5 + 1 + r3)*16 + e];
    }
    __syncthreads();
    int tx = tid&31, ty = tid>>5;
    int d0 = blockIdx.x*32, r0 = blockIdx.y*32;
    const size_t X = (size_t)Rsz*Dsz;
    #pragma unroll
    for (int dr = 0; dr < 4; dr++) {
        int rr = ty + dr*8;
        float a[6] = {0.f,0.f,0.f,0.f,0.f,0.f};
        #pragma unroll
        for (int n = 0; n < 16; n++) {
            float p = pool[(size_t)n*X + (size_t)(r0+rr)*Dsz + d0+tx];
            #pragma unroll
            for (int sl = 0; sl < 6; sl++) a[sl] += ws[sl][n]*p;
        }
        #pragma unroll
        for (int sl = 0; sl < 6; sl++) tile[sl][rr][tx] = a[sl];
    }
    __syncthreads();
    #pragma unroll
    for (int dr = 0; dr < 4; dr++) {
        int dd = ty + dr*8;
        #pragma unroll
        for (int sl = 0; sl < 6; sl++)
            out[(size_t)sl*X + (size_t)(d0+dd)*Rsz + r0+tx] = tile[sl][tx][dd];
    }
}

// ---------------- tf32 tensor-core GEMM (NT): C = alpha*A[M,K] x B[N,K]^T ---
// K = row stride (full depth); Kloop = this CTA's K extent.
// SPLITK2: blockIdx.z = batch*2 + khalf; epilogue atomicAdd into pre-zeroed C.
template<bool RESID, bool SPLITK2>
__global__ __launch_bounds__(256) void tgemm_kernel(
    const float* __restrict__ A, const float* __restrict__ Bm,
    const float* __restrict__ Rsrc, float* __restrict__ C,
    int M, int N, int K, int Kloop, float alpha,
    size_t sA, size_t sB, size_t sC, size_t sR)
{
    __shared__ uint32_t As[4*8*4*32];
    __shared__ uint32_t Bs[4*16*2*32];
    int bz, koff;
    if (SPLITK2) { bz = blockIdx.z >> 1; koff = (blockIdx.z & 1)*Kloop; }
    else         { bz = blockIdx.z;      koff = 0; }
    A += (size_t)bz*sA + koff; Bm += (size_t)bz*sB + koff;
    C += (size_t)bz*sC; if (RESID) Rsrc += (size_t)bz*sR;
    int tid = threadIdx.x, lane = tid&31, warp = tid>>5;
    int wm = warp>>2, wn = warp&3;
    int bm = blockIdx.y<<7, bn = blockIdx.x<<7;

    float c[4][4][4];
    #pragma unroll
    for (int i=0;i<4;i++)
        #pragma unroll
        for(int j=0;j<4;j++)
            #pragma unroll
            for(int f=0;f<4;f++) c[i][j][f]=0.f;

    int row = tid>>1;
    int qb  = (tid&1)*4;
    const float* Aro = A + (size_t)(bm+row)*K;
    const float* Bro = Bm + (size_t)(bn+row)*K;
    int amt = row>>4, arm = row&15;
    int bnt = row>>3, brn = row&7;
    uint32_t* Abase = As + ((amt*4 + (arm>>3))*32) + (arm&7)*4;
    uint32_t* Bbase = Bs + (bnt*2)*32 + brn*4;

    for (int k0 = 0; k0 < Kloop; k0 += 32) {
        #pragma unroll
        for (int i = 0; i < 4; i++) {
            int q = qb + i;
            float4 v = *(const float4*)(Aro + k0 + q*4);
            uint4 u;
            asm("cvt.rna.tf32.f32 %0,%1;":"=r"(u.x):"f"(v.x));
            asm("cvt.rna.tf32.f32 %0,%1;":"=r"(u.y):"f"(v.y));
            asm("cvt.rna.tf32.f32 %0,%1;":"=r"(u.z):"f"(v.z));
            asm("cvt.rna.tf32.f32 %0,%1;":"=r"(u.w):"f"(v.w));
            *(uint4*)(Abase + (q>>1)*1024 + (q&1)*64) = u;
        }
        #pragma unroll
        for (int i = 0; i < 4; i++) {
            int q = qb + i;
            float4 v = *(const float4*)(Bro + k0 + q*4);
            uint4 u;
            asm("cvt.rna.tf32.f32 %0,%1;":"=r"(u.x):"f"(v.x));
            asm("cvt.rna.tf32.f32 %0,%1;":"=r"(u.y):"f"(v.y));
            asm("cvt.rna.tf32.f32 %0,%1;":"=r"(u.z):"f"(v.z));
            asm("cvt.rna.tf32.f32 %0,%1;":"=r"(u.w):"f"(v.w));
            *(uint4*)(Bbase + (q>>1)*1024 + (q&1)*32) = u;
        }
        __syncthreads();
        #pragma unroll
        for (int k8 = 0; k8 < 4; k8++) {
            uint32_t a[4][4], b[4][2];
            #pragma unroll
            for (int mt = 0; mt < 4; mt++) {
                const uint32_t* p = As + k8*1024 + ((wm*4+mt)*4)*32 + lane;
                a[mt][0]=p[0]; a[mt][1]=p[32]; a[mt][2]=p[64]; a[mt][3]=p[96];
            }
            #pragma unroll
            for (int nt = 0; nt < 4; nt++) {
                const uint32_t* p = Bs + k8*1024 + ((wn*4+nt)*2)*32 + lane;
                b[nt][0]=p[0]; b[nt][1]=p[32];
            }
            #pragma unroll
            for (int mt = 0; mt < 4; mt++)
                #pragma unroll
                for (int nt = 0; nt < 4; nt++)
                    asm volatile(
                        "mma.sync.aligned.m16n8k8.row.col.f32.tf32.tf32.f32 "
                        "{%0,%1,%2,%3}, {%4,%5,%6,%7}, {%8,%9}, {%0,%1,%2,%3};"
                        : "+f"(c[mt][nt][0]), "+f"(c[mt][nt][1]),
                          "+f"(c[mt][nt][2]), "+f"(c[mt][nt][3])
                        : "r"(a[mt][0]), "r"(a[mt][1]), "r"(a[mt][2]), "r"(a[mt][3]),
                          "r"(b[nt][0]), "r"(b[nt][1]));
        }
        __syncthreads();
    }
    int g = lane>>2, tg = lane&3;
    #pragma unroll
    for (int mt = 0; mt < 4; mt++) {
        size_t r0 = (size_t)(bm + wm*64 + mt*16 + g);
        size_t r1 = r0 + 8;
        #pragma unroll
        for (int nt = 0; nt < 4; nt++) {
            int col = bn + wn*32 + nt*8 + tg*2;
            if (SPLITK2) {
                atomicAdd(&C[r0*N + col],   alpha*c[mt][nt][0]);
                atomicAdd(&C[r0*N + col+1], alpha*c[mt][nt][1]);
                atomicAdd(&C[r1*N + col],   alpha*c[mt][nt][2]);
                atomicAdd(&C[r1*N + col+1], alpha*c[mt][nt][3]);
            } else {
                float2 v0 = make_float2(alpha*c[mt][nt][0], alpha*c[mt][nt][1]);
                float2 v1 = make_float2(alpha*c[mt][nt][2], alpha*c[mt][nt][3]);
                if (RESID) {
                    float2 q0 = *(const float2*)&Rsrc[r0*N + col];
                    float2 q1 = *(const float2*)&Rsrc[r1*N + col];
                    v0.x += q0.x; v0.y += q0.y; v1.x += q1.x; v1.y += q1.y;
                }
                *(float2*)&C[r0*N + col] = v0;
                *(float2*)&C[r1*N + col] = v1;
            }
        }
    }
}

// ---------------- bf16 tensor-core causal flash attention (dh=64) -----------
__device__ __forceinline__ void mma16816(float* c, const uint32_t* a,
                                         uint32_t b0, uint32_t b1) {
    asm volatile("mma.sync.aligned.m16n8k16.row.col.f32.bf16.bf16.f32 "
        "{%0,%1,%2,%3}, {%4,%5,%6,%7}, {%8,%9}, {%0,%1,%2,%3};"
        : "+f"(c[0]),"+f"(c[1]),"+f"(c[2]),"+f"(c[3])
        : "r"(a[0]),"r"(a[1]),"r"(a[2]),"r"(a[3]), "r"(b0),"r"(b1));
}

__global__ __launch_bounds__(256) void flash_mma_kernel(
    const float* __restrict__ Q, const float* __restrict__ Kt,
    const float* __restrict__ V, float* __restrict__ O)
{
    __shared__ __nv_bfloat16 Ks[64][72];
    __shared__ __nv_bfloat16 Vs[64][72];
    int qt = blockIdx.x, h = blockIdx.y, b = blockIdx.z;
    int tid = threadIdx.x, lane = tid&31, w = tid>>5;
    int g = lane>>2, tg = lane&3;
    const size_t base = ((size_t)b*Ssz)*Dsz + h*DHsz;
    int qb = qt*128;
    int frow = tid>>2, fd0 = (tid&3)*16;
    int lrow = (w&3)*16 + g;
    int row0 = qb + w*16 + g;

    uint32_t qa[4][4];
    {
        const float* src = Q + base + (size_t)(qb+frow)*Dsz + fd0;
        #pragma unroll
        for (int j = 0; j < 4; j++) {
            float4 v = *(const float4*)(src + j*4);
            *(__nv_bfloat162*)&Ks[frow][fd0+j*4]   = __floats2bfloat162_rn(v.x*0.125f, v.y*0.125f);
            *(__nv_bfloat162*)&Ks[frow][fd0+j*4+2] = __floats2bfloat162_rn(v.z*0.125f, v.w*0.125f);
        }
    }
    __syncthreads();
    if (w < 4) {
        #pragma unroll
        for (int ks = 0; ks < 4; ks++) {
            qa[ks][0] = *(const uint32_t*)&Ks[lrow  ][ks*16+2*tg];
            qa[ks][1] = *(const uint32_t*)&Ks[lrow+8][ks*16+2*tg];
            qa[ks][2] = *(const uint32_t*)&Ks[lrow  ][ks*16+2*tg+8];
            qa[ks][3] = *(const uint32_t*)&Ks[lrow+8][ks*16+2*tg+8];
        }
    }
    __syncthreads();
    {
        const float* src = Q + base + (size_t)(qb+64+frow)*Dsz + fd0;
        #pragma unroll
        for (int j = 0; j < 4; j++) {
            float4 v = *(const float4*)(src + j*4);
            *(__nv_bfloat162*)&Ks[frow][fd0+j*4]   = __floats2bfloat162_rn(v.x*0.125f, v.y*0.125f);
            *(__nv_bfloat162*)&Ks[frow][fd0+j*4+2] = __floats2bfloat162_rn(v.z*0.125f, v.w*0.125f);
        }
    }
    __syncthreads();
    if (w >= 4) {
        #pragma unroll
        for (int ks = 0; ks < 4; ks++) {
            qa[ks][0] = *(const uint32_t*)&Ks[lrow  ][ks*16+2*tg];
            qa[ks][1] = *(const uint32_t*)&Ks[lrow+8][ks*16+2*tg];
            qa[ks][2] = *(const uint32_t*)&Ks[lrow  ][ks*16+2*tg+8];
            qa[ks][3] = *(const uint32_t*)&Ks[lrow+8][ks*16+2*tg+8];
        }
    }

    float o[8][4];
    #pragma unroll
    for (int nt = 0; nt < 8; nt++)
        o[nt][0]=o[nt][1]=o[nt][2]=o[nt][3]=0.f;
    float m0=-1e30f, m1=-1e30f, l0=0.f, l1=0.f;

    int ntiles = 2*qt + 2;
    for (int kt = 0; kt < ntiles; kt++) {
        int k0 = kt*64;
        __syncthreads();
        {
            const float* ksrc = Kt + base + (size_t)(k0+frow)*Dsz + fd0;
            const float* vsrc = V  + base + (size_t)(k0+frow)*Dsz + fd0;
            #pragma unroll
            for (int j = 0; j < 4; j++) {
                float4 kv = *(const float4*)(ksrc + j*4);
                *(__nv_bfloat162*)&Ks[frow][fd0+j*4]   = __floats2bfloat162_rn(kv.x, kv.y);
                *(__nv_bfloat162*)&Ks[frow][fd0+j*4+2] = __floats2bfloat162_rn(kv.z, kv.w);
                float4 vv = *(const float4*)(vsrc + j*4);
                Vs[fd0+j*4  ][frow] = __float2bfloat16(vv.x);
                Vs[fd0+j*4+1][frow] = __float2bfloat16(vv.y);
                Vs[fd0+j*4+2][frow] = __float2bfloat16(vv.z);
                Vs[fd0+j*4+3][frow] = __float2bfloat16(vv.w);
            }
        }
        __syncthreads();

        float sc[8][4];
        #pragma unroll
        for (int nt = 0; nt < 8; nt++) {
            sc[nt][0]=sc[nt][1]=sc[nt][2]=sc[nt][3]=0.f;
            #pragma unroll
            for (int ks = 0; ks < 4; ks++) {
                uint32_t kb0 = *(const uint32_t*)&Ks[nt*8+g][ks*16+2*tg];
                uint32_t kb1 = *(const uint32_t*)&Ks[nt*8+g][ks*16+2*tg+8];
                mma16816(sc[nt], qa[ks], kb0, kb1);
            }
        }
        if (kt >= 2*qt) {
            #pragma unroll
            for (int nt = 0; nt < 8; nt++) {
                int col = k0 + nt*8 + 2*tg;
                if (col   > row0)   sc[nt][0] = -1e30f;
                if (col+1 > row0)   sc[nt][1] = -1e30f;
                if (col   > row0+8) sc[nt][2] = -1e30f;
                if (col+1 > row0+8) sc[nt][3] = -1e30f;
            }
        }
        float mx0 = -1e30f, mx1 = -1e30f;
        #pragma unroll
        for (int nt = 0; nt < 8; nt++) {
            mx0 = fmaxf(mx0, fmaxf(sc[nt][0], sc[nt][1]));
            mx1 = fmaxf(mx1, fmaxf(sc[nt][2], sc[nt][3]));
        }
        mx0 = fmaxf(mx0, __shfl_xor_sync(0xffffffffu, mx0, 1));
        mx0 = fmaxf(mx0, __shfl_xor_sync(0xffffffffu, mx0, 2));
        mx1 = fmaxf(mx1, __shfl_xor_sync(0xffffffffu, mx1, 1));
        mx1 = fmaxf(mx1, __shfl_xor_sync(0xffffffffu, mx1, 2));
        float nm0 = fmaxf(m0, mx0), nm1 = fmaxf(m1, mx1);
        float c0 = fexp(m0 - nm0), c1 = fexp(m1 - nm1);
        m0 = nm0; m1 = nm1;

        uint32_t pa[4][4];
        float s0 = 0.f, s1 = 0.f;
        #pragma unroll
        for (int nt = 0; nt < 8; nt++) {
            float e0 = fexp(sc[nt][0]-m0), e1 = fexp(sc[nt][1]-m0);
            float e2 = fexp(sc[nt][2]-m1), e3 = fexp(sc[nt][3]-m1);
            s0 += e0+e1; s1 += e2+e3;
            int ks = nt>>1, hi = (nt&1)*2;
            pa[ks][hi+0] = pack_bf16x2(e0, e1);
            pa[ks][hi+1] = pack_bf16x2(e2, e3);
        }
        s0 += __shfl_xor_sync(0xffffffffu, s0, 1);
        s0 += __shfl_xor_sync(0xffffffffu, s0, 2);
        s1 += __shfl_xor_sync(0xffffffffu, s1, 1);
        s1 += __shfl_xor_sync(0xffffffffu, s1, 2);
        l0 = l0*c0 + s0; l1 = l1*c1 + s1;

        #pragma unroll
        for (int nt = 0; nt < 8; nt++) {
            o[nt][0]*=c0; o[nt][1]*=c0; o[nt][2]*=c1; o[nt][3]*=c1;
            #pragma unroll
            for (int ks = 0; ks < 4; ks++) {
                uint32_t vb0 = *(const uint32_t*)&Vs[nt*8+g][ks*16+2*tg];
                uint32_t vb1 = *(const uint32_t*)&Vs[nt*8+g][ks*16+2*tg+8];
                mma16816(o[nt], pa[ks], vb0, vb1);
            }
        }
    }
    float i0 = 1.f/l0, i1 = 1.f/l1;
    #pragma unroll
    for (int nt = 0; nt < 8; nt++) {
        float2 v0 = make_float2(o[nt][0]*i0, o[nt][1]*i0);
        float2 v1 = make_float2(o[nt][2]*i1, o[nt][3]*i1);
        *(float2*)&O[base + (size_t)row0*Dsz + nt*8 + 2*tg]     = v0;
        *(float2*)&O[base + (size_t)(row0+8)*Dsz + nt*8 + 2*tg] = v1;
    }
}

// ---------------- top-8 (register-local) + softmax + gather + residual ------
__global__ __launch_bounds__(256) void topk_mem_kernel(
    const float* __restrict__ MS, const float* __restrict__ KV,
    float* __restrict__ OUT)
{
    int s = blockIdx.x, bq = blockIdx.y, tid = threadIdx.x;
    int lane = tid & 31, w = tid >> 5;
    __shared__ float rv[8];
    __shared__ int   ri[8];
    __shared__ float topv[8];
    __shared__ int   topi[8];
    __shared__ float tw[8];
    const float* row = MS + ((size_t)bq*Ssz + s)*NKk;

    float lv[8]; int li[8];
    #pragma unroll
    for (int k = 0; k < 8; k++) { lv[k] = -1e30f; li[k] = NKk; }
    #pragma unroll
    for (int j = 0; j < 16; j++) {
        int idx = tid + j*256;
        float cv = row[idx]; int ci = idx;
        if (cv > lv[7]) {
            #pragma unroll
            for (int k = 0; k < 8; k++) {
                if (cv > lv[k]) {
                    float tv = lv[k]; int ti = li[k];
                    lv[k] = cv; li[k] = ci;
                    cv = tv; ci = ti;
                }
            }
        }
    }

    for (int it = 0; it < 8; it++) {
        float hv = lv[0]; int hi = li[0];
        #pragma unroll
        for (int o = 16; o > 0; o >>= 1) {
            float ov = __shfl_xor_sync(0xffffffffu, hv, o);
            int   oi = __shfl_xor_sync(0xffffffffu, hi, o);
            if (ov > hv || (ov == hv && oi < hi)) { hv = ov; hi = oi; }
        }
        if (lane == 0) { rv[w] = hv; ri[w] = hi; }
        __syncthreads();
        if (tid == 0) {
            float bv = rv[0]; int bi = ri[0];
            #pragma unroll
            for (int k = 1; k < 8; k++)
                if (rv[k] > bv || (rv[k] == bv && ri[k] < bi)) { bv = rv[k]; bi = ri[k]; }
            topv[it] = bv; topi[it] = bi;
        }
        __syncthreads();
        if (li[0] == topi[it]) {
            #pragma unroll
            for (int k = 0; k < 7; k++) { lv[k] = lv[k+1]; li[k] = li[k+1]; }
            lv[7] = -1e30f; li[7] = NKk;
        }
        __syncthreads();
    }
    if (tid == 0) {
        float mx = topv[0]; float se = 0.f;
        #pragma unroll
        for (int k = 0; k < 8; k++) { tw[k] = __expf(topv[k]-mx); se += tw[k]; }
        float inv = 1.f/se;
        #pragma unroll
        for (int k = 0; k < 8; k++) tw[k] *= inv;
    }
    __syncthreads();
    float w0 = tw[0], w1 = tw[1], w2 = tw[2], w3 = tw[3];
    float w4 = tw[4], w5 = tw[5], w6 = tw[6], w7 = tw[7];
    size_t i0 = (size_t)topi[0]*Dsz, i1 = (size_t)topi[1]*Dsz;
    size_t i2 = (size_t)topi[2]*Dsz, i3 = (size_t)topi[3]*Dsz;
    size_t i4 = (size_t)topi[4]*Dsz, i5 = (size_t)topi[5]*Dsz;
    size_t i6 = (size_t)topi[6]*Dsz, i7 = (size_t)topi[7]*Dsz;
    float* o = OUT + ((size_t)bq*Ssz + s)*Dsz;
    for (int d = tid; d < Dsz; d += 256) {
        float a = o[d];
        a = fmaf(w0, KV[i0+d], a); a = fmaf(w1, KV[i1+d], a);
        a = fmaf(w2, KV[i2+d], a); a = fmaf(w3, KV[i3+d], a);
        a = fmaf(w4, KV[i4+d], a); a = fmaf(w5, KV[i5+d], a);
        a = fmaf(w6, KV[i6+d], a); a = fmaf(w7, KV[i7+d], a);
        o[d] = a;
    }
}

// ---------------- launch ----------------------------------------------------
extern "C" void kernel_launch(void* const* d_in, const int* in_sizes, int n_in,
                              void* d_out, int out_size)
{
    const float* x    = (const float*)d_in[0];
    const float* imp  = (const float*)d_in[1];
    const float* Wc   = (const float*)d_in[2];
    const float* WQ   = (const float*)d_in[3];
    const float* WK   = (const float*)d_in[4];
    const float* WV   = (const float*)d_in[5];
    const float* Wm   = (const float*)d_in[6];
    const float* cn   = (const float*)d_in[7];
    const float* pool = (const float*)d_in[8];
    const float* kK   = (const float*)d_in[9];
    const float* kV   = (const float*)d_in[10];
    const float* WO   = (const float*)d_in[11];
    const float* g1   = (const float*)d_in[12];
    const float* b1   = (const float*)d_in[13];
    const float* g2   = (const float*)d_in[14];
    const float* b2   = (const float*)d_in[15];
    float* out = (float*)d_out;

    static float* base = nullptr;
    if (!base) cudaGetSymbolAddress((void**)&base, g_scratch);

    float* nx   = base + OFF_NX;
    float* nx2  = base + OFF_NX2;
    float* scp  = base + OFF_SC;
    float* mcp  = base + OFF_MC;
    float* ep   = base + OFF_E;
    float* hp   = base + OFF_H;
    float* qmp  = base + OFF_QM;
    float* qkvp = base + OFF_QKV;
    float* aop  = base + OFF_AO;
    float* msp  = base + OFF_MS;
    float* accP = base + OFF_ACC;
    float* wptr = base + OFF_W;

    const size_t SD = (size_t)Ssz*Dsz;
    const size_t SR = (size_t)Ssz*Rsz;
    const size_t RD = (size_t)Rsz*Dsz;
    const size_t BSD = (size_t)Bsz*Ssz*Dsz;
    const size_t SNK = (size_t)Ssz*NKk;
    const int BSR = Bsz*Ssz*Rsz;

    zero_kernel<<<(NSLICE*Bsz*5*16 + 255)/256, 256>>>(accP, NSLICE*Bsz*5*16);
    zero_kernel<<<(BSR + 255)/256, 256>>>(hp, BSR);
    ln_route8_kernel<<<dim3(Ssz/8, Bsz), 256>>>(x, imp, Wc, WQ, WK, WV, g1, b1,
                                                nx, accP, 4, 0);
    finalize_w_kernel<<<1, 256>>>(accP, wptr, 0, 4);
    combine_cT_kernel<<<dim3(Dsz/32, Rsz/32), 256>>>(wptr, cn, scp, 0);
    combine_eT_kernel<<<dim3(Dsz/32, Rsz/32), 256>>>(wptr, pool, ep);
    // h = nx @ scT^T  (split-K=2: 128 CTAs)
    tgemm_kernel<false,true><<<dim3(Rsz/128, Ssz/128, Bsz*2), 256>>>(nx, scp,
        nullptr, hp, Ssz, Rsz, Dsz, Dsz/2, 1.f, SD, RD, SR, 0);
    for (int r3 = 0; r3 < 3; r3++)
        tgemm_kernel<false,false><<<dim3(Dsz/128, Ssz/128, Bsz), 256>>>(hp,
            ep + (size_t)r3*Bsz*RD, nullptr, qkvp + (size_t)r3*BSD,
            Ssz, Dsz, Rsz, Rsz, 1.f, SR, RD, SD, 0);
    flash_mma_kernel<<<dim3(Ssz/128, Hsz, Bsz), 256>>>(qkvp, qkvp + BSD,
                                                       qkvp + 2*BSD, aop);
    tgemm_kernel<true,false><<<dim3(Dsz/128, Ssz/128, Bsz), 256>>>(aop, WO, x, out,
        Ssz, Dsz, Dsz, Dsz, 1.f, SD, 0, SD, SD);
    ln_route8_kernel<<<dim3(Ssz/8, Bsz), 256>>>(out, imp, Wm, Wm, Wm, Wm, g2, b2,
                                                nx2, accP, 1, 4);
    finalize_w_kernel<<<1, 256>>>(accP, wptr, 4, 1);
    combine_cT_kernel<<<dim3(Dsz/32, Rsz/32), 256>>>(wptr, cn, mcp, 4);
    zero_kernel<<<(BSR + 255)/256, 256>>>(qmp, BSR);
    // Qm = nx2 @ mcT^T  (split-K=2)
    tgemm_kernel<false,true><<<dim3(Rsz/128, Ssz/128, Bsz*2), 256>>>(nx2, mcp,
        nullptr, qmp, Ssz, Rsz, Dsz, Dsz/2, 1.f, SD, RD, SR, 0);
    tgemm_kernel<false,false><<<dim3(NKk/128, Ssz/128, Bsz), 256>>>(qmp, kK,
        nullptr, msp, Ssz, NKk, Rsz, Rsz, 0.0625f, SR, 0, SNK, 0);
    topk_mem_kernel<<<dim3(Ssz, Bsz), 256>>>(msp, kV, out);
}